// round 13
// baseline (speedup 1.0000x reference)
#include <cuda_runtime.h>
#include <math.h>
#include <stdint.h>

#define B_  8
#define LP_ 1000
#define NC_ 64
#define D_  128
#define E_  320
#define NTILE_ 100
#define ITILE_ 10
typedef long long ll;

// ---------------- scratch (device globals) ----------------------------------
__device__ __align__(16) uint2 g_Qhl[B_*LP_*64];
__device__ __align__(16) uint2 g_Khl[B_*LP_*64];
__device__ __align__(16) uint2 g_Chl[B_*NC_*64];
__device__ __align__(16) uint2 g_wkp[64*D_];
__device__ __align__(16) uint2 g_wvp[64*D_];
__device__ __align__(16) uint2 g_wop[64*D_];
__device__ __align__(16) uint2 g_jpp[64*D_];
__device__ __align__(16) float g_Wq0[E_*D_];
__device__ __align__(16) float g_Vf [B_*LP_*D_];
__device__ __align__(16) float g_AV0[B_*LP_*D_];
__device__ __align__(16) float g_AV1[B_*LP_*D_];
__device__ __align__(16) float g_M0 [B_*LP_];
__device__ __align__(16) float g_L0 [B_*LP_];
__device__ __align__(16) float g_M1 [B_*LP_];
__device__ __align__(16) float g_L1 [B_*LP_];
__device__ __align__(16) float g_pf [B_*LP_*D_];
__device__ __align__(16) float g_P  [B_*LP_*D_];
__device__ __align__(16) float g_A  [B_*LP_*NC_];
__device__ __align__(16) float g_bq [D_];
__device__ __align__(16) float g_Apart[B_*16];
__device__ __align__(16) float g_part[B_*NTILE_*D_];
__device__ __align__(16) float g_cp [B_*D_];
__device__ __align__(16) float g_h1 [B_*1024];
__device__ __align__(16) float g_h2 [B_*1024];
__device__ __align__(16) float g_h3 [B_*256];

// ---------------- bf16 helpers -----------------------------------------------
__device__ __forceinline__ uint32_t packbf(float x, float y) {  // lo=x, hi=y
    uint32_t r;
    asm("cvt.rn.bf16x2.f32 %0, %1, %2;" : "=r"(r) : "f"(y), "f"(x));
    return r;
}
__device__ __forceinline__ float lowbf(uint32_t h)  { return __uint_as_float(h << 16); }
__device__ __forceinline__ float highbf(uint32_t h) { return __uint_as_float(h & 0xFFFF0000u); }
__device__ __forceinline__ uint2 cvt_pair(float x, float y) {
    uint32_t h = packbf(x, y);
    uint32_t l = packbf(x - lowbf(h), y - highbf(h));
    return make_uint2(h, l);
}
__device__ __forceinline__ void mma_bf16(float* d, const uint32_t* a, const uint32_t* b) {
    asm volatile(
        "mma.sync.aligned.m16n8k16.row.col.f32.bf16.bf16.f32 "
        "{%0,%1,%2,%3}, {%4,%5,%6,%7}, {%8,%9}, {%0,%1,%2,%3};\n"
        : "+f"(d[0]), "+f"(d[1]), "+f"(d[2]), "+f"(d[3])
        : "r"(a[0]), "r"(a[1]), "r"(a[2]), "r"(a[3]), "r"(b[0]), "r"(b[1]));
}

// ---------------- unified GEMM body: 64(M) x 128(N) tile, BK=16, bf16x3 -----
// AMODE: 0=A fp32, 1=fp32+relu, 4=flash-combine(Af,Af2+M/L)
// BMODE: 0=pre-paired uint2 [kp][n], 1=fp32 K-major pack-on-fly
// EPI: 0=fp32 out, 1=pair uint2 out.  K multiple of 16, N=128.
template<int AMODE, int BMODE, int EPI>
__device__ __forceinline__ void gemm_body(
    const float* __restrict__ Af, const float* __restrict__ Af2,
    const float* __restrict__ M0p, const float* __restrict__ L0p,
    const float* __restrict__ M1p, const float* __restrict__ L1p,
    const uint2* __restrict__ Bh, const float* __restrict__ Bf,
    const float* __restrict__ bias, float* __restrict__ Cf, uint2* __restrict__ Ch,
    int M, int N, int K, int lda, int ldb,
    float alpha, int m0, uint2* As, uint2* Bs)
{
    constexpr int ASN = 64 * 12;
    constexpr int BSN = 8 * 132;

    int t = threadIdx.x, warp = t >> 5, lane = t & 31;
    int g = lane >> 2, l3 = lane & 3;
    int wm = (warp & 1) * 32, wn = (warp >> 1) * 32;

    float acc[2][4][4] = {};

    int ar = t >> 2, akf = (t & 3) * 4, akp = (t & 3) * 2;
    int bk = t >> 5, bn = (t & 31) * 4;

    int kt = K >> 4;
    uint4 ua, ub0, ub1;

    auto loadA = [&](int k0) {
        int gm = m0 + ar;
        float4 rv = make_float4(0.f, 0.f, 0.f, 0.f);
        if (gm < M) {
            int gk = k0 + akf;
            rv = *(const float4*)(Af + (ll)gm * lda + gk);
            if (AMODE == 4) {
                float4 r2 = *(const float4*)(Af2 + (ll)gm * lda + gk);
                float m0v = M0p[gm], m1v = M1p[gm];
                float mm = fmaxf(m0v, m1v);
                float a0 = __expf(m0v - mm), a1 = __expf(m1v - mm);
                float inv = 1.f / (a0 * L0p[gm] + a1 * L1p[gm]);
                rv.x = (rv.x * a0 + r2.x * a1) * inv;
                rv.y = (rv.y * a0 + r2.y * a1) * inv;
                rv.z = (rv.z * a0 + r2.z * a1) * inv;
                rv.w = (rv.w * a0 + r2.w * a1) * inv;
            }
            if (AMODE == 1) {
                rv.x = fmaxf(rv.x, 0.f); rv.y = fmaxf(rv.y, 0.f);
                rv.z = fmaxf(rv.z, 0.f); rv.w = fmaxf(rv.w, 0.f);
            }
        }
        uint2 p0 = cvt_pair(rv.x, rv.y), p1 = cvt_pair(rv.z, rv.w);
        ua = make_uint4(p0.x, p0.y, p1.x, p1.y);
    };
    auto loadB = [&](int k0) {
        if (BMODE == 0) {
            const uint2* p = Bh + (ll)((k0 >> 1) + bk) * N + bn;
            ub0 = *(const uint4*)p;
            ub1 = *(const uint4*)(p + 2);
        } else {
            int gk0 = k0 + 2 * bk, gk1 = gk0 + 1;
            float4 r0 = *(const float4*)(Bf + (ll)gk0 * ldb + bn);
            float4 r1 = *(const float4*)(Bf + (ll)gk1 * ldb + bn);
            uint2 q0 = cvt_pair(r0.x, r1.x), q1 = cvt_pair(r0.y, r1.y);
            uint2 q2 = cvt_pair(r0.z, r1.z), q3 = cvt_pair(r0.w, r1.w);
            ub0 = make_uint4(q0.x, q0.y, q1.x, q1.y);
            ub1 = make_uint4(q2.x, q2.y, q3.x, q3.y);
        }
    };
    auto storeA = [&](int s) { *(uint4*)&As[s * ASN + ar * 12 + akp] = ua; };
    auto storeB = [&](int s) {
        *(uint4*)&Bs[s * BSN + bk * 132 + bn]     = ub0;
        *(uint4*)&Bs[s * BSN + bk * 132 + bn + 2] = ub1;
    };

    loadA(0); loadB(0);
    storeA(0); storeB(0);
    __syncthreads();

    for (int it = 0; it < kt; it++) {
        int s = it & 1;
        if (it + 1 < kt) { loadA((it + 1) << 4); loadB((it + 1) << 4); }

        uint32_t ahi[2][4], alo[2][4];
        #pragma unroll
        for (int mi = 0; mi < 2; mi++) {
            int rr = wm + mi * 16 + g;
            uint2 x0 = As[s * ASN + rr * 12 + l3];
            uint2 x1 = As[s * ASN + (rr + 8) * 12 + l3];
            uint2 x2 = As[s * ASN + rr * 12 + l3 + 4];
            uint2 x3 = As[s * ASN + (rr + 8) * 12 + l3 + 4];
            ahi[mi][0] = x0.x; alo[mi][0] = x0.y;
            ahi[mi][1] = x1.x; alo[mi][1] = x1.y;
            ahi[mi][2] = x2.x; alo[mi][2] = x2.y;
            ahi[mi][3] = x3.x; alo[mi][3] = x3.y;
        }
        uint32_t bhi[4][2], blo[4][2];
        #pragma unroll
        for (int ni = 0; ni < 4; ni++) {
            int cc = wn + ni * 8 + g;
            uint2 y0 = Bs[s * BSN + l3 * 132 + cc];
            uint2 y1 = Bs[s * BSN + (l3 + 4) * 132 + cc];
            bhi[ni][0] = y0.x; blo[ni][0] = y0.y;
            bhi[ni][1] = y1.x; blo[ni][1] = y1.y;
        }
        #pragma unroll
        for (int mi = 0; mi < 2; mi++)
            #pragma unroll
            for (int ni = 0; ni < 4; ni++) {
                mma_bf16(acc[mi][ni], ahi[mi], bhi[ni]);
                mma_bf16(acc[mi][ni], ahi[mi], blo[ni]);
                mma_bf16(acc[mi][ni], alo[mi], bhi[ni]);
            }
        if (it + 1 < kt) { storeA(s ^ 1); storeB(s ^ 1); }
        __syncthreads();
    }

    #pragma unroll
    for (int mi = 0; mi < 2; mi++)
        #pragma unroll
        for (int ni = 0; ni < 4; ni++) {
            int r0 = m0 + wm + mi * 16 + g;
            int c0 = wn + ni * 8 + 2 * l3;
            float b0 = 0.f, b1 = 0.f;
            if (bias) { b0 = bias[c0]; b1 = bias[c0 + 1]; }
            float v00 = (acc[mi][ni][0] + b0) * alpha;
            float v01 = (acc[mi][ni][1] + b1) * alpha;
            float v10 = (acc[mi][ni][2] + b0) * alpha;
            float v11 = (acc[mi][ni][3] + b1) * alpha;
            if (EPI == 0) {
                if (r0 < M)     *(float2*)(Cf + (ll)r0 * N + c0)       = make_float2(v00, v01);
                if (r0 + 8 < M) *(float2*)(Cf + (ll)(r0 + 8) * N + c0) = make_float2(v10, v11);
            } else {
                if (r0 < M)     Ch[(ll)r0 * (N >> 1) + (c0 >> 1)]       = cvt_pair(v00, v01);
                if (r0 + 8 < M) Ch[(ll)(r0 + 8) * (N >> 1) + (c0 >> 1)] = cvt_pair(v10, v11);
            }
        }
}

// ---------------- flash attention (split-KV): partial O + (m,l) --------------
__global__ void __launch_bounds__(128)
flash_attn(const uint2* __restrict__ Qhl, const uint2* __restrict__ Khl,
           const float* __restrict__ Vf,
           float* __restrict__ AV0, float* __restrict__ AV1,
           float* __restrict__ M0, float* __restrict__ L0,
           float* __restrict__ M1, float* __restrict__ L1)
{
    __shared__ __align__(16) uint2 Ks[32 * 68];
    __shared__ __align__(16) uint2 Vs[16 * 132];

    int b = blockIdx.z, half = blockIdx.y, m0t = blockIdx.x * 64;
    int kvOff = half * 512;
    int t = threadIdx.x, w = t >> 5, lane = t & 31;
    int g = lane >> 2, l3 = lane & 3;
    int r0 = m0t + w * 16 + g, r1 = r0 + 8;

    uint32_t qhi[8][4], qlo[8][4];
    {
        const uint2* Q0 = Qhl + ((ll)b * LP_ + r0) * 64;
        const uint2* Q1 = Qhl + ((ll)b * LP_ + r1) * 64;
        #pragma unroll
        for (int s = 0; s < 8; s++) {
            uint2 u0 = make_uint2(0u,0u), u2 = u0, u1 = u0, u3 = u0;
            if (r0 < LP_) { u0 = Q0[8*s + l3]; u2 = Q0[8*s + l3 + 4]; }
            if (r1 < LP_) { u1 = Q1[8*s + l3]; u3 = Q1[8*s + l3 + 4]; }
            qhi[s][0] = u0.x; qlo[s][0] = u0.y;
            qhi[s][1] = u1.x; qlo[s][1] = u1.y;
            qhi[s][2] = u2.x; qlo[s][2] = u2.y;
            qhi[s][3] = u3.x; qlo[s][3] = u3.y;
        }
    }

    float accO[16][4] = {};
    float m0_ = -1e30f, m1_ = -1e30f, l0_ = 0.f, l1_ = 0.f;

    int kvp = t >> 3, dseg = (t & 7) * 16;

    for (int iter = 0; iter < 16; iter++) {
        int kb = kvOff + iter * 32;
        uint4 kreg[8];
        #pragma unroll
        for (int j = 0; j < 8; j++) {
            int idx = t + 128 * j, row = idx >> 5, q4 = idx & 31;
            int gkv = kb + row;
            kreg[j] = (gkv < LP_)
                ? *(const uint4*)(Khl + ((ll)b * LP_ + gkv) * 64 + q4 * 2)
                : make_uint4(0u,0u,0u,0u);
        }
        float4 fA[4], fB[4];
        {
            int rA = kb + 2 * kvp, rB = rA + 1;
            #pragma unroll
            for (int dd = 0; dd < 4; dd++) {
                fA[dd] = (rA < LP_) ? *(const float4*)(Vf + ((ll)b * LP_ + rA) * 128 + dseg + 4*dd)
                                    : make_float4(0.f,0.f,0.f,0.f);
                fB[dd] = (rB < LP_) ? *(const float4*)(Vf + ((ll)b * LP_ + rB) * 128 + dseg + 4*dd)
                                    : make_float4(0.f,0.f,0.f,0.f);
            }
        }
        __syncthreads();
        #pragma unroll
        for (int j = 0; j < 8; j++) {
            int idx = t + 128 * j, row = idx >> 5, q4 = idx & 31;
            *(uint4*)&Ks[row * 68 + q4 * 2] = kreg[j];
        }
        #pragma unroll
        for (int dd = 0; dd < 4; dd++) {
            uint2 p0 = cvt_pair(fA[dd].x, fB[dd].x);
            uint2 p1 = cvt_pair(fA[dd].y, fB[dd].y);
            uint2 p2 = cvt_pair(fA[dd].z, fB[dd].z);
            uint2 p3 = cvt_pair(fA[dd].w, fB[dd].w);
            uint2* vp = &Vs[kvp * 132 + dseg + 4*dd];
            *(uint4*)vp       = make_uint4(p0.x, p0.y, p1.x, p1.y);
            *(uint4*)(vp + 2) = make_uint4(p2.x, p2.y, p3.x, p3.y);
        }
        __syncthreads();

        float sacc[4][4] = {};
        #pragma unroll
        for (int nt = 0; nt < 4; nt++) {
            int krow = nt * 8 + g;
            #pragma unroll
            for (int s = 0; s < 8; s++) {
                uint2 y0 = Ks[krow * 68 + 8*s + l3];
                uint2 y1 = Ks[krow * 68 + 8*s + l3 + 4];
                uint32_t bh[2] = {y0.x, y1.x}, bl[2] = {y0.y, y1.y};
                mma_bf16(sacc[nt], qhi[s], bh);
                mma_bf16(sacc[nt], qhi[s], bl);
                mma_bf16(sacc[nt], qlo[s], bh);
            }
        }

        float cm0 = -1e30f, cm1 = -1e30f;
        #pragma unroll
        for (int nt = 0; nt < 4; nt++) {
            cm0 = fmaxf(cm0, fmaxf(sacc[nt][0], sacc[nt][1]));
            cm1 = fmaxf(cm1, fmaxf(sacc[nt][2], sacc[nt][3]));
        }
        cm0 = fmaxf(cm0, __shfl_xor_sync(0xffffffffu, cm0, 1));
        cm0 = fmaxf(cm0, __shfl_xor_sync(0xffffffffu, cm0, 2));
        cm1 = fmaxf(cm1, __shfl_xor_sync(0xffffffffu, cm1, 1));
        cm1 = fmaxf(cm1, __shfl_xor_sync(0xffffffffu, cm1, 2));
        float mn0 = fmaxf(m0_, cm0), mn1 = fmaxf(m1_, cm1);
        float sc0 = __expf(m0_ - mn0), sc1 = __expf(m1_ - mn1);
        m0_ = mn0; m1_ = mn1;

        uint32_t phi[2][4], plo[2][4];
        float rs0 = 0.f, rs1 = 0.f;
        #pragma unroll
        for (int nt = 0; nt < 4; nt++) {
            int c0 = kb + nt * 8 + 2 * l3;
            bool v0 = c0 < LP_, v1 = (c0 + 1) < LP_;
            float p00 = v0 ? __expf(sacc[nt][0] - mn0) : 0.f;
            float p01 = v1 ? __expf(sacc[nt][1] - mn0) : 0.f;
            float p10 = v0 ? __expf(sacc[nt][2] - mn1) : 0.f;
            float p11 = v1 ? __expf(sacc[nt][3] - mn1) : 0.f;
            rs0 += p00 + p01; rs1 += p10 + p11;
            uint2 hA = cvt_pair(p00, p01);
            uint2 hB = cvt_pair(p10, p11);
            int s2 = nt >> 1, o = (nt & 1) * 2;
            phi[s2][o]     = hA.x; plo[s2][o]     = hA.y;
            phi[s2][o + 1] = hB.x; plo[s2][o + 1] = hB.y;
        }
        rs0 += __shfl_xor_sync(0xffffffffu, rs0, 1);
        rs0 += __shfl_xor_sync(0xffffffffu, rs0, 2);
        rs1 += __shfl_xor_sync(0xffffffffu, rs1, 1);
        rs1 += __shfl_xor_sync(0xffffffffu, rs1, 2);
        l0_ = l0_ * sc0 + rs0;
        l1_ = l1_ * sc1 + rs1;
        #pragma unroll
        for (int dt = 0; dt < 16; dt++) {
            accO[dt][0] *= sc0; accO[dt][1] *= sc0;
            accO[dt][2] *= sc1; accO[dt][3] *= sc1;
        }

        #pragma unroll
        for (int dt = 0; dt < 16; dt++) {
            #pragma unroll
            for (int s2 = 0; s2 < 2; s2++) {
                int vr = 8 * s2 + l3;
                uint2 y0 = Vs[vr * 132 + dt * 8 + g];
                uint2 y1 = Vs[(vr + 4) * 132 + dt * 8 + g];
                uint32_t bh[2] = {y0.x, y1.x}, bl[2] = {y0.y, y1.y};
                mma_bf16(accO[dt], phi[s2], bh);
                mma_bf16(accO[dt], phi[s2], bl);
                mma_bf16(accO[dt], plo[s2], bh);
            }
        }
    }

    float* AVp = half ? AV1 : AV0;
    float* Mo  = half ? M1 : M0;
    float* Lo  = half ? L1 : L0;
    #pragma unroll
    for (int dt = 0; dt < 16; dt++) {
        int c = dt * 8 + 2 * l3;
        if (r0 < LP_)
            *(float2*)(AVp + ((ll)b * LP_ + r0) * 128 + c) =
                make_float2(accO[dt][0], accO[dt][1]);
        if (r1 < LP_)
            *(float2*)(AVp + ((ll)b * LP_ + r1) * 128 + c) =
                make_float2(accO[dt][2], accO[dt][3]);
    }
    if (l3 == 0) {
        if (r0 < LP_) { Mo[(ll)b * LP_ + r0] = m0_; Lo[(ll)b * LP_ + r0] = l0_; }
        if (r1 < LP_) { Mo[(ll)b * LP_ + r1] = m1_; Lo[(ll)b * LP_ + r1] = l1_; }
    }
}

// ---------------- prep_all: repacks + bq + Wq0 GEMM + Chl GEMM ----------------
// grid (32, 8): y=0..3 repack wk/wv/wo/jp, y=4 bq, y=5 Wq0 (x<5), y=6 Chl (x<8)
__global__ void __launch_bounds__(256)
prep_all(const float* wq_w, const float* wk_w, const float* wv_w,
         const float* wo_w, const float* jp_w, const float* jc_w,
         uint2* wkp, uint2* wvp, uint2* wop, uint2* jpp,
         const float* emb_b, const float* wq_b, float* bq,
         const float* emb_w, float* Wq0,
         const float* cf, const float* jc_b, uint2* Chl)
{
    __shared__ __align__(16) uint2 As[2 * 64 * 12];
    __shared__ __align__(16) uint2 Bs[2 * 8 * 132];
    int y = blockIdx.y;
    if (y == 5) {
        if (blockIdx.x >= 5) return;
        gemm_body<0, 1, 0>(emb_w, nullptr, nullptr, nullptr, nullptr, nullptr,
            nullptr, wq_w, nullptr, Wq0, nullptr,
            E_, D_, D_, D_, D_, 1.f, blockIdx.x * 64, As, Bs);
        return;
    }
    if (y == 6) {
        if (blockIdx.x >= 8) return;
        gemm_body<1, 1, 1>(cf, nullptr, nullptr, nullptr, nullptr, nullptr,
            nullptr, jc_w, jc_b, nullptr, Chl,
            B_*NC_, D_, D_, D_, D_, 1.f, blockIdx.x * 64, As, Bs);
        return;
    }
    if (y == 4) {
        if (blockIdx.x == 0 && threadIdx.x < 128) {
            int n = threadIdx.x;
            float s = wq_b[n];
            for (int k = 0; k < D_; k++) s = fmaf(emb_b[k], wq_w[k * D_ + n], s);
            bq[n] = s;
        }
        return;
    }
    int i = blockIdx.x * 256 + threadIdx.x;
    const float* s; uint2* d;
    switch (y) {
        case 0: s = wk_w; d = wkp; break;
        case 1: s = wv_w; d = wvp; break;
        case 2: s = wo_w; d = wop; break;
        default: s = jp_w; d = jpp; break;
    }
    int kp = i >> 7, n = i & 127;
    d[i] = cvt_pair(s[(2 * kp) * D_ + n], s[(2 * kp + 1) * D_ + n]);
}

__global__ void __launch_bounds__(256, 3)
gemm_qkv(const float* __restrict__ in_pe, const float* __restrict__ Wq0,
         const float* __restrict__ bq, uint2* __restrict__ Qhl,
         const float* __restrict__ in_pfx,
         const uint2* __restrict__ wkp, const float* __restrict__ wk_b,
         uint2* __restrict__ Khl,
         const uint2* __restrict__ wvp, const float* __restrict__ wv_b,
         float* __restrict__ Vf, float inv_sqrt_d)
{
    __shared__ __align__(16) uint2 As[2 * 64 * 12];
    __shared__ __align__(16) uint2 Bs[2 * 8 * 132];
    int m0 = blockIdx.y * 64;
    if (blockIdx.z == 0)
        gemm_body<0, 1, 1>(in_pe, nullptr, nullptr, nullptr, nullptr, nullptr,
            nullptr, Wq0, bq, nullptr, Qhl,
            B_*LP_, D_, E_, E_, D_, inv_sqrt_d, m0, As, Bs);
    else if (blockIdx.z == 1)
        gemm_body<0, 0, 1>(in_pfx, nullptr, nullptr, nullptr, nullptr, nullptr,
            wkp, nullptr, wk_b, nullptr, Khl,
            B_*LP_, D_, D_, D_, D_, 1.f, m0, As, Bs);
    else
        gemm_body<0, 0, 0>(in_pfx, nullptr, nullptr, nullptr, nullptr, nullptr,
            wvp, nullptr, wv_b, Vf, nullptr,
            B_*LP_, D_, D_, D_, D_, 1.f, m0, As, Bs);
}

// pf = combine(AV0,AV1;m,l) @ wo + b
__global__ void __launch_bounds__(256, 3)
gemm_wo(const float* __restrict__ AV0, const float* __restrict__ AV1,
        const float* __restrict__ M0, const float* __restrict__ L0,
        const float* __restrict__ M1, const float* __restrict__ L1,
        const uint2* __restrict__ wop, const float* __restrict__ wo_b,
        float* __restrict__ pf)
{
    __shared__ __align__(16) uint2 As[2 * 64 * 12];
    __shared__ __align__(16) uint2 Bs[2 * 8 * 132];
    gemm_body<4, 0, 0>(AV0, AV1, M0, L0, M1, L1,
        wop, nullptr, wo_b, pf, nullptr,
        B_*LP_, D_, D_, D_, D_, 1.f, blockIdx.y * 64, As, Bs);
}

// P = relu(pf) @ jp + b  (Chl moved to prep_all)
__global__ void __launch_bounds__(256, 3)
gemm_pc(const float* __restrict__ pf, const uint2* __restrict__ jpp,
        const float* __restrict__ jp_b, float* __restrict__ P)
{
    __shared__ __align__(16) uint2 As[2 * 64 * 12];
    __shared__ __align__(16) uint2 Bs[2 * 8 * 132];
    gemm_body<1, 0, 0>(pf, nullptr, nullptr, nullptr, nullptr, nullptr,
        jpp, nullptr, jp_b, P, nullptr,
        B_*LP_, D_, D_, D_, D_, 1.f, blockIdx.y * 64, As, Bs);
}

// ---------------- A-logits: bf16x3 64x64 GEMM + sigmoid + partial sums -------
__global__ void __launch_bounds__(256, 3)
alogits_kernel(const float* __restrict__ Pm, const uint2* __restrict__ Chl,
               float* __restrict__ Aout, float* __restrict__ Apart)
{
    __shared__ __align__(16) uint2 As[2][768];
    __shared__ __align__(16) uint2 Bs[2][768];
    __shared__ float red[256];

    int b = blockIdx.y, mt = blockIdx.x, m0 = mt * 64;
    const float* A = Pm + (ll)b * LP_ * D_;
    const uint2* Bh = Chl + (ll)b * NC_ * 64;
    float* C = Aout + (ll)b * LP_ * NC_;
    int t = threadIdx.x, warp = t >> 5, lane = t & 31;
    int g = lane >> 2, l3 = lane & 3;
    int wm = (warp & 1) * 32, wn = (warp >> 1) * 16;

    float acc[2][2][4] = {};
    int ar = t >> 2, akf = (t & 3) * 4, akp = (t & 3) * 2;
    uint4 ua, ub;

    auto loadAB = [&](int k0) {
        int gm = m0 + ar;
        float4 rv = make_float4(0.f, 0.f, 0.f, 0.f);
        if (gm < LP_) rv = *(const float4*)(A + (ll)gm * D_ + k0 + akf);
        uint2 p0 = cvt_pair(rv.x, rv.y), p1 = cvt_pair(rv.z, rv.w);
        ua = make_uint4(p0.x, p0.y, p1.x, p1.y);
        ub = *(const uint4*)(Bh + (ll)ar * 64 + (k0 >> 1) + akp);
    };
    auto storeAB = [&](int s) {
        *(uint4*)&As[s][ar * 12 + akp] = ua;
        *(uint4*)&Bs[s][ar * 12 + akp] = ub;
    };
    loadAB(0); storeAB(0);
    __syncthreads();

    for (int it = 0; it < 8; it++) {
        int s = it & 1;
        if (it < 7) loadAB((it + 1) << 4);
        uint32_t ahi[2][4], alo[2][4];
        #pragma unroll
        for (int mi = 0; mi < 2; mi++) {
            int rr = wm + mi * 16 + g;
            uint2 x0 = As[s][rr * 12 + l3];
            uint2 x1 = As[s][(rr + 8) * 12 + l3];
            uint2 x2 = As[s][rr * 12 + l3 + 4];
            uint2 x3 = As[s][(rr + 8) * 12 + l3 + 4];
            ahi[mi][0] = x0.x; alo[mi][0] = x0.y;
            ahi[mi][1] = x1.x; alo[mi][1] = x1.y;
            ahi[mi][2] = x2.x; alo[mi][2] = x2.y;
            ahi[mi][3] = x3.x; alo[mi][3] = x3.y;
        }
        uint32_t bhi[2][2], blo[2][2];
        #pragma unroll
        for (int ni = 0; ni < 2; ni++) {
            int cc = wn + ni * 8 + g;
            uint2 y0 = Bs[s][cc * 12 + l3];
            uint2 y1 = Bs[s][cc * 12 + l3 + 4];
            bhi[ni][0] = y0.x; blo[ni][0] = y0.y;
            bhi[ni][1] = y1.x; blo[ni][1] = y1.y;
        }
        #pragma unroll
        for (int mi = 0; mi < 2; mi++)
            #pragma unroll
            for (int ni = 0; ni < 2; ni++) {
                mma_bf16(acc[mi][ni], ahi[mi], bhi[ni]);
                mma_bf16(acc[mi][ni], ahi[mi], blo[ni]);
                mma_bf16(acc[mi][ni], alo[mi], bhi[ni]);
            }
        if (it < 7) storeAB(s ^ 1);
        __syncthreads();
    }

    float tsum = 0.f;
    #pragma unroll
    for (int mi = 0; mi < 2; mi++)
        #pragma unroll
        for (int ni = 0; ni < 2; ni++) {
            int r0 = m0 + wm + mi * 16 + g;
            int c0 = wn + ni * 8 + 2 * l3;
            if (r0 < LP_) {
                float v0 = 1.f / (1.f + __expf(-acc[mi][ni][0]));
                float v1 = 1.f / (1.f + __expf(-acc[mi][ni][1]));
                *(float2*)(C + (ll)r0 * NC_ + c0) = make_float2(v0, v1);
                tsum += v0 + v1;
            }
            if (r0 + 8 < LP_) {
                float v0 = 1.f / (1.f + __expf(-acc[mi][ni][2]));
                float v1 = 1.f / (1.f + __expf(-acc[mi][ni][3]));
                *(float2*)(C + (ll)(r0 + 8) * NC_ + c0) = make_float2(v0, v1);
                tsum += v0 + v1;
            }
        }
    red[t] = tsum; __syncthreads();
    for (int s2 = 128; s2 > 0; s2 >>= 1) {
        if (t < s2) red[t] += red[t + s2];
        __syncthreads();
    }
    if (t == 0) Apart[b * 16 + mt] = red[0];
}

// ---------------- tanh outer-product weighted reduction ---------------------
__global__ void tanh_outer_kernel(const float* __restrict__ pf,
                                  const float* __restrict__ cf,
                                  const float* __restrict__ A,
                                  float* __restrict__ part)
{
    int b = blockIdx.y, tile = blockIdx.x;
    int d = threadIdx.x;  // 128
    __shared__ float cfs[NC_ * D_];
    for (int i = threadIdx.x; i < NC_ * D_; i += 128)
        cfs[i] = cf[(ll)b * NC_ * D_ + i];
    __syncthreads();
    float acc = 0.f;
    int i0 = tile * ITILE_;
    for (int i = i0; i < i0 + ITILE_; i++) {
        float pv = pf[((ll)b * LP_ + i) * D_ + d];
        const float* Ar = A + ((ll)b * LP_ + i) * NC_;
        #pragma unroll 4
        for (int k = 0; k < NC_; k++) {
            float w = Ar[k];
            float x = pv * cfs[k * D_ + d];
            float th;
            asm("tanh.approx.f32 %0, %1;" : "=f"(th) : "f"(x));
            acc = fmaf(th, w, acc);
        }
    }
    part[((ll)b * NTILE_ + tile) * D_ + d] = acc;
}

__global__ void cp_reduce_kernel(const float* __restrict__ part,
                                 const float* __restrict__ Apart,
                                 float* __restrict__ cp)
{
    int b = blockIdx.x;
    int d = threadIdx.x;  // 128
    float as = 0.f;
    #pragma unroll
    for (int j = 0; j < 16; j++) as += Apart[b * 16 + j];
    float s = 0.f;
    for (int t2 = 0; t2 < NTILE_; t2++)
        s += part[((ll)b * NTILE_ + t2) * D_ + d];
    cp[b * D_ + d] = s / as;
}

// ---------------- skinny GEMM (M = 8 rows) -----------------------------------
template<bool RELU_OUT>
__global__ void __launch_bounds__(256)
skinny_gemm(const float* __restrict__ A, const float* __restrict__ W,
            const float* __restrict__ bias, float* __restrict__ C,
            int N, int K)
{
    __shared__ float As[8 * 1024];
    __shared__ float red[8][8][32];
    int t = threadIdx.x;
    for (int i = t; i < 8 * K; i += 256) As[i] = A[i];
    __syncthreads();
    int n = blockIdx.x * 32 + (t & 31);
    int ks = t >> 5;
    int kseg = K >> 3;
    float acc[8] = {};
    if (n < N) {
        for (int k = ks * kseg; k < (ks + 1) * kseg; k++) {
            float w = W[(ll)k * N + n];
            #pragma unroll
            for (int m = 0; m < 8; m++) acc[m] = fmaf(As[m * K + k], w, acc[m]);
        }
    }
    #pragma unroll
    for (int m = 0; m < 8; m++) red[ks][m][t & 31] = acc[m];
    __syncthreads();
    int m = t >> 5, lnn = t & 31;
    int nn = blockIdx.x * 32 + lnn;
    if (nn < N) {
        float s = 0.f;
        #pragma unroll
        for (int j = 0; j < 8; j++) s += red[j][m][lnn];
        s += bias[nn];
        if (RELU_OUT) s = fmaxf(s, 0.f);
        C[(ll)m * N + nn] = s;
    }
}

// ---------------- launch ------------------------------------------------------
extern "C" void kernel_launch(void* const* d_in, const int* in_sizes, int n_in,
                              void* d_out, int out_size)
{
    const float* in_pe  = (const float*)d_in[0];
    const float* in_pfx = (const float*)d_in[1];
    const float* in_cf  = (const float*)d_in[2];
    const float* emb_w = (const float*)d_in[3];  const float* emb_b = (const float*)d_in[4];
    const float* wq_w  = (const float*)d_in[5];  const float* wq_b  = (const float*)d_in[6];
    const float* wk_w  = (const float*)d_in[7];  const float* wk_b  = (const float*)d_in[8];
    const float* wv_w  = (const float*)d_in[9];  const float* wv_b  = (const float*)d_in[10];
    const float* wo_w  = (const float*)d_in[11]; const float* wo_b  = (const float*)d_in[12];
    const float* jp_w  = (const float*)d_in[13]; const float* jp_b  = (const float*)d_in[14];
    const float* jc_w  = (const float*)d_in[15]; const float* jc_b  = (const float*)d_in[16];
    const float* c1_w  = (const float*)d_in[17]; const float* c1_b  = (const float*)d_in[18];
    const float* c2_w  = (const float*)d_in[19]; const float* c2_b  = (const float*)d_in[20];
    const float* c3_w  = (const float*)d_in[21]; const float* c3_b  = (const float*)d_in[22];
    const float* c4_w  = (const float*)d_in[23]; const float* c4_b  = (const float*)d_in[24];

    uint2 *Qhl, *Khl, *Chl, *wkp, *wvp, *wop, *jpp;
    float *Wq0, *Vf, *AV0, *AV1, *M0, *L0, *M1, *L1, *pf, *P, *A, *bq, *Apart,
          *part, *cp, *h1, *h2, *h3;
    cudaGetSymbolAddress((void**)&Qhl,  g_Qhl);
    cudaGetSymbolAddress((void**)&Khl,  g_Khl);
    cudaGetSymbolAddress((void**)&Chl,  g_Chl);
    cudaGetSymbolAddress((void**)&wkp,  g_wkp);
    cudaGetSymbolAddress((void**)&wvp,  g_wvp);
    cudaGetSymbolAddress((void**)&wop,  g_wop);
    cudaGetSymbolAddress((void**)&jpp,  g_jpp);
    cudaGetSymbolAddress((void**)&Wq0,  g_Wq0);
    cudaGetSymbolAddress((void**)&Vf,   g_Vf);
    cudaGetSymbolAddress((void**)&AV0,  g_AV0);
    cudaGetSymbolAddress((void**)&AV1,  g_AV1);
    cudaGetSymbolAddress((void**)&M0,   g_M0);
    cudaGetSymbolAddress((void**)&L0,   g_L0);
    cudaGetSymbolAddress((void**)&M1,   g_M1);
    cudaGetSymbolAddress((void**)&L1,   g_L1);
    cudaGetSymbolAddress((void**)&pf,   g_pf);
    cudaGetSymbolAddress((void**)&P,    g_P);
    cudaGetSymbolAddress((void**)&A,    g_A);
    cudaGetSymbolAddress((void**)&bq,   g_bq);
    cudaGetSymbolAddress((void**)&Apart,g_Apart);
    cudaGetSymbolAddress((void**)&part, g_part);
    cudaGetSymbolAddress((void**)&cp,   g_cp);
    cudaGetSymbolAddress((void**)&h1,   g_h1);
    cudaGetSymbolAddress((void**)&h2,   g_h2);
    cudaGetSymbolAddress((void**)&h3,   g_h3);

    const float inv_sqrt_d = 0.088388347648318440550f;  // 1/sqrt(128)

    // 0. prep: 4 weight repacks + bq + Wq0 GEMM + Chl GEMM (one launch)
    prep_all<<<dim3(32,7),256>>>(wq_w, wk_w, wv_w, wo_w, jp_w, jc_w,
                                 wkp, wvp, wop, jpp,
                                 emb_b, wq_b, bq, emb_w, Wq0,
                                 in_cf, jc_b, Chl);
    // 1. Q/K/V
    gemm_qkv<<<dim3(1,125,3),256>>>(in_pe, Wq0, bq, Qhl,
                                    in_pfx, wkp, wk_b, Khl,
                                    wvp, wv_b, Vf, inv_sqrt_d);
    // 2. split-KV flash attention -> partial O + (m,l)
    flash_attn<<<dim3(16,2,B_),128>>>(Qhl, Khl, Vf, AV0, AV1, M0, L0, M1, L1);
    // 3. pf = combine(AV partials) @ wo + b
    gemm_wo<<<dim3(1,125),256>>>(AV0, AV1, M0, L0, M1, L1, wop, wo_b, pf);
    // 4. P
    gemm_pc<<<dim3(1,125),256>>>(pf, jpp, jp_b, P);
    // 5. A = sigmoid(P @ C^T) + partial sums
    alogits_kernel<<<dim3(16,B_),256>>>(P, Chl, A, Apart);
    // 6. tanh outer product partials
    tanh_outer_kernel<<<dim3(NTILE_,B_),128>>>(pf, in_cf, A, part);
    // 7. reduce + normalize
    cp_reduce_kernel<<<B_,128>>>(part, Apart, cp);
    // 8-11. classifier MLP
    skinny_gemm<true ><<<32,256>>>(cp, c1_w, c1_b, h1, 1024, D_);
    skinny_gemm<true ><<<32,256>>>(h1, c2_w, c2_b, h2, 1024, 1024);
    skinny_gemm<true ><<<8, 256>>>(h2, c3_w, c3_b, h3, 256, 1024);
    skinny_gemm<false><<<1, 256>>>(h3, c4_w, c4_b, (float*)d_out, 1, 256);
}

// round 14
// speedup vs baseline: 1.1179x; 1.1179x over previous
#include <cuda_runtime.h>
#include <math.h>
#include <stdint.h>

#define B_  8
#define LP_ 1000
#define NC_ 64
#define D_  128
#define E_  320
#define NTILE_ 100
#define ITILE_ 10
typedef long long ll;

// ---------------- scratch (device globals) ----------------------------------
__device__ __align__(16) uint2 g_Qhl[B_*LP_*64];
__device__ __align__(16) uint2 g_Khl[B_*LP_*64];
__device__ __align__(16) uint2 g_Chl[B_*NC_*64];
__device__ __align__(16) uint2 g_wkp[64*D_];
__device__ __align__(16) uint2 g_wvp[64*D_];
__device__ __align__(16) uint2 g_wop[64*D_];
__device__ __align__(16) uint2 g_jpp[64*D_];
__device__ __align__(16) float g_Wq0[E_*D_];
__device__ __align__(16) float g_Vf [B_*LP_*D_];
__device__ __align__(16) float g_AV0[B_*LP_*D_];
__device__ __align__(16) float g_AV1[B_*LP_*D_];
__device__ __align__(16) float g_M0 [B_*LP_];
__device__ __align__(16) float g_L0 [B_*LP_];
__device__ __align__(16) float g_M1 [B_*LP_];
__device__ __align__(16) float g_L1 [B_*LP_];
__device__ __align__(16) float g_pf [B_*LP_*D_];
__device__ __align__(16) float g_P  [B_*LP_*D_];
__device__ __align__(16) float g_A  [B_*LP_*NC_];
__device__ __align__(16) float g_bq [D_];
__device__ __align__(16) float g_Apart[B_*16];
__device__ __align__(16) float g_part[B_*NTILE_*D_];
__device__ __align__(16) float g_cp [B_*D_];
__device__ __align__(16) float g_h1 [B_*1024];
__device__ __align__(16) float g_h2 [B_*1024];
__device__ __align__(16) float g_h3 [B_*256];

// ---------------- bf16 helpers -----------------------------------------------
__device__ __forceinline__ uint32_t packbf(float x, float y) {  // lo=x, hi=y
    uint32_t r;
    asm("cvt.rn.bf16x2.f32 %0, %1, %2;" : "=r"(r) : "f"(y), "f"(x));
    return r;
}
__device__ __forceinline__ float lowbf(uint32_t h)  { return __uint_as_float(h << 16); }
__device__ __forceinline__ float highbf(uint32_t h) { return __uint_as_float(h & 0xFFFF0000u); }
__device__ __forceinline__ uint2 cvt_pair(float x, float y) {
    uint32_t h = packbf(x, y);
    uint32_t l = packbf(x - lowbf(h), y - highbf(h));
    return make_uint2(h, l);
}
__device__ __forceinline__ void mma_bf16(float* d, const uint32_t* a, const uint32_t* b) {
    asm volatile(
        "mma.sync.aligned.m16n8k16.row.col.f32.bf16.bf16.f32 "
        "{%0,%1,%2,%3}, {%4,%5,%6,%7}, {%8,%9}, {%0,%1,%2,%3};\n"
        : "+f"(d[0]), "+f"(d[1]), "+f"(d[2]), "+f"(d[3])
        : "r"(a[0]), "r"(a[1]), "r"(a[2]), "r"(a[3]), "r"(b[0]), "r"(b[1]));
}

// ---------------- unified GEMM body: 64(M) x 128(N) tile, BK=16, bf16x3 -----
// AMODE: 0=A fp32, 1=fp32+relu, 4=flash-combine(Af,Af2+M/L)
// BMODE: 0=pre-paired uint2 [kp][n], 1=fp32 K-major pack-on-fly
// EPI: 0=fp32 out, 1=pair uint2 out.  K multiple of 16, N=128.
template<int AMODE, int BMODE, int EPI>
__device__ __forceinline__ void gemm_body(
    const float* __restrict__ Af, const float* __restrict__ Af2,
    const float* __restrict__ M0p, const float* __restrict__ L0p,
    const float* __restrict__ M1p, const float* __restrict__ L1p,
    const uint2* __restrict__ Bh, const float* __restrict__ Bf,
    const float* __restrict__ bias, float* __restrict__ Cf, uint2* __restrict__ Ch,
    int M, int N, int K, int lda, int ldb,
    float alpha, int m0, uint2* As, uint2* Bs)
{
    constexpr int ASN = 64 * 12;
    constexpr int BSN = 8 * 132;

    int t = threadIdx.x, warp = t >> 5, lane = t & 31;
    int g = lane >> 2, l3 = lane & 3;
    int wm = (warp & 1) * 32, wn = (warp >> 1) * 32;

    float acc[2][4][4] = {};

    int ar = t >> 2, akf = (t & 3) * 4, akp = (t & 3) * 2;
    int bk = t >> 5, bn = (t & 31) * 4;

    int kt = K >> 4;
    uint4 ua, ub0, ub1;

    auto loadA = [&](int k0) {
        int gm = m0 + ar;
        float4 rv = make_float4(0.f, 0.f, 0.f, 0.f);
        if (gm < M) {
            int gk = k0 + akf;
            rv = *(const float4*)(Af + (ll)gm * lda + gk);
            if (AMODE == 4) {
                float4 r2 = *(const float4*)(Af2 + (ll)gm * lda + gk);
                float m0v = M0p[gm], m1v = M1p[gm];
                float mm = fmaxf(m0v, m1v);
                float a0 = __expf(m0v - mm), a1 = __expf(m1v - mm);
                float inv = 1.f / (a0 * L0p[gm] + a1 * L1p[gm]);
                rv.x = (rv.x * a0 + r2.x * a1) * inv;
                rv.y = (rv.y * a0 + r2.y * a1) * inv;
                rv.z = (rv.z * a0 + r2.z * a1) * inv;
                rv.w = (rv.w * a0 + r2.w * a1) * inv;
            }
            if (AMODE == 1) {
                rv.x = fmaxf(rv.x, 0.f); rv.y = fmaxf(rv.y, 0.f);
                rv.z = fmaxf(rv.z, 0.f); rv.w = fmaxf(rv.w, 0.f);
            }
        }
        uint2 p0 = cvt_pair(rv.x, rv.y), p1 = cvt_pair(rv.z, rv.w);
        ua = make_uint4(p0.x, p0.y, p1.x, p1.y);
    };
    auto loadB = [&](int k0) {
        if (BMODE == 0) {
            const uint2* p = Bh + (ll)((k0 >> 1) + bk) * N + bn;
            ub0 = *(const uint4*)p;
            ub1 = *(const uint4*)(p + 2);
        } else {
            int gk0 = k0 + 2 * bk, gk1 = gk0 + 1;
            float4 r0 = *(const float4*)(Bf + (ll)gk0 * ldb + bn);
            float4 r1 = *(const float4*)(Bf + (ll)gk1 * ldb + bn);
            uint2 q0 = cvt_pair(r0.x, r1.x), q1 = cvt_pair(r0.y, r1.y);
            uint2 q2 = cvt_pair(r0.z, r1.z), q3 = cvt_pair(r0.w, r1.w);
            ub0 = make_uint4(q0.x, q0.y, q1.x, q1.y);
            ub1 = make_uint4(q2.x, q2.y, q3.x, q3.y);
        }
    };
    auto storeA = [&](int s) { *(uint4*)&As[s * ASN + ar * 12 + akp] = ua; };
    auto storeB = [&](int s) {
        *(uint4*)&Bs[s * BSN + bk * 132 + bn]     = ub0;
        *(uint4*)&Bs[s * BSN + bk * 132 + bn + 2] = ub1;
    };

    loadA(0); loadB(0);
    storeA(0); storeB(0);
    __syncthreads();

    for (int it = 0; it < kt; it++) {
        int s = it & 1;
        if (it + 1 < kt) { loadA((it + 1) << 4); loadB((it + 1) << 4); }

        uint32_t ahi[2][4], alo[2][4];
        #pragma unroll
        for (int mi = 0; mi < 2; mi++) {
            int rr = wm + mi * 16 + g;
            uint2 x0 = As[s * ASN + rr * 12 + l3];
            uint2 x1 = As[s * ASN + (rr + 8) * 12 + l3];
            uint2 x2 = As[s * ASN + rr * 12 + l3 + 4];
            uint2 x3 = As[s * ASN + (rr + 8) * 12 + l3 + 4];
            ahi[mi][0] = x0.x; alo[mi][0] = x0.y;
            ahi[mi][1] = x1.x; alo[mi][1] = x1.y;
            ahi[mi][2] = x2.x; alo[mi][2] = x2.y;
            ahi[mi][3] = x3.x; alo[mi][3] = x3.y;
        }
        uint32_t bhi[4][2], blo[4][2];
        #pragma unroll
        for (int ni = 0; ni < 4; ni++) {
            int cc = wn + ni * 8 + g;
            uint2 y0 = Bs[s * BSN + l3 * 132 + cc];
            uint2 y1 = Bs[s * BSN + (l3 + 4) * 132 + cc];
            bhi[ni][0] = y0.x; blo[ni][0] = y0.y;
            bhi[ni][1] = y1.x; blo[ni][1] = y1.y;
        }
        #pragma unroll
        for (int mi = 0; mi < 2; mi++)
            #pragma unroll
            for (int ni = 0; ni < 4; ni++) {
                mma_bf16(acc[mi][ni], ahi[mi], bhi[ni]);
                mma_bf16(acc[mi][ni], ahi[mi], blo[ni]);
                mma_bf16(acc[mi][ni], alo[mi], bhi[ni]);
            }
        if (it + 1 < kt) { storeA(s ^ 1); storeB(s ^ 1); }
        __syncthreads();
    }

    #pragma unroll
    for (int mi = 0; mi < 2; mi++)
        #pragma unroll
        for (int ni = 0; ni < 4; ni++) {
            int r0 = m0 + wm + mi * 16 + g;
            int c0 = wn + ni * 8 + 2 * l3;
            float b0 = 0.f, b1 = 0.f;
            if (bias) { b0 = bias[c0]; b1 = bias[c0 + 1]; }
            float v00 = (acc[mi][ni][0] + b0) * alpha;
            float v01 = (acc[mi][ni][1] + b1) * alpha;
            float v10 = (acc[mi][ni][2] + b0) * alpha;
            float v11 = (acc[mi][ni][3] + b1) * alpha;
            if (EPI == 0) {
                if (r0 < M)     *(float2*)(Cf + (ll)r0 * N + c0)       = make_float2(v00, v01);
                if (r0 + 8 < M) *(float2*)(Cf + (ll)(r0 + 8) * N + c0) = make_float2(v10, v11);
            } else {
                if (r0 < M)     Ch[(ll)r0 * (N >> 1) + (c0 >> 1)]       = cvt_pair(v00, v01);
                if (r0 + 8 < M) Ch[(ll)(r0 + 8) * (N >> 1) + (c0 >> 1)] = cvt_pair(v10, v11);
            }
        }
}

// ---------------- flash attention (split-KV): partial O + (m,l) --------------
__global__ void __launch_bounds__(128)
flash_attn(const uint2* __restrict__ Qhl, const uint2* __restrict__ Khl,
           const float* __restrict__ Vf,
           float* __restrict__ AV0, float* __restrict__ AV1,
           float* __restrict__ M0, float* __restrict__ L0,
           float* __restrict__ M1, float* __restrict__ L1)
{
    __shared__ __align__(16) uint2 Ks[32 * 68];
    __shared__ __align__(16) uint2 Vs[16 * 132];

    int b = blockIdx.z, half = blockIdx.y, m0t = blockIdx.x * 64;
    int kvOff = half * 512;
    int t = threadIdx.x, w = t >> 5, lane = t & 31;
    int g = lane >> 2, l3 = lane & 3;
    int r0 = m0t + w * 16 + g, r1 = r0 + 8;

    uint32_t qhi[8][4], qlo[8][4];
    {
        const uint2* Q0 = Qhl + ((ll)b * LP_ + r0) * 64;
        const uint2* Q1 = Qhl + ((ll)b * LP_ + r1) * 64;
        #pragma unroll
        for (int s = 0; s < 8; s++) {
            uint2 u0 = make_uint2(0u,0u), u2 = u0, u1 = u0, u3 = u0;
            if (r0 < LP_) { u0 = Q0[8*s + l3]; u2 = Q0[8*s + l3 + 4]; }
            if (r1 < LP_) { u1 = Q1[8*s + l3]; u3 = Q1[8*s + l3 + 4]; }
            qhi[s][0] = u0.x; qlo[s][0] = u0.y;
            qhi[s][1] = u1.x; qlo[s][1] = u1.y;
            qhi[s][2] = u2.x; qlo[s][2] = u2.y;
            qhi[s][3] = u3.x; qlo[s][3] = u3.y;
        }
    }

    float accO[16][4] = {};
    float m0_ = -1e30f, m1_ = -1e30f, l0_ = 0.f, l1_ = 0.f;

    int kvp = t >> 3, dseg = (t & 7) * 16;

    for (int iter = 0; iter < 16; iter++) {
        int kb = kvOff + iter * 32;
        uint4 kreg[8];
        #pragma unroll
        for (int j = 0; j < 8; j++) {
            int idx = t + 128 * j, row = idx >> 5, q4 = idx & 31;
            int gkv = kb + row;
            kreg[j] = (gkv < LP_)
                ? *(const uint4*)(Khl + ((ll)b * LP_ + gkv) * 64 + q4 * 2)
                : make_uint4(0u,0u,0u,0u);
        }
        float4 fA[4], fB[4];
        {
            int rA = kb + 2 * kvp, rB = rA + 1;
            #pragma unroll
            for (int dd = 0; dd < 4; dd++) {
                fA[dd] = (rA < LP_) ? *(const float4*)(Vf + ((ll)b * LP_ + rA) * 128 + dseg + 4*dd)
                                    : make_float4(0.f,0.f,0.f,0.f);
                fB[dd] = (rB < LP_) ? *(const float4*)(Vf + ((ll)b * LP_ + rB) * 128 + dseg + 4*dd)
                                    : make_float4(0.f,0.f,0.f,0.f);
            }
        }
        __syncthreads();
        #pragma unroll
        for (int j = 0; j < 8; j++) {
            int idx = t + 128 * j, row = idx >> 5, q4 = idx & 31;
            *(uint4*)&Ks[row * 68 + q4 * 2] = kreg[j];
        }
        #pragma unroll
        for (int dd = 0; dd < 4; dd++) {
            uint2 p0 = cvt_pair(fA[dd].x, fB[dd].x);
            uint2 p1 = cvt_pair(fA[dd].y, fB[dd].y);
            uint2 p2 = cvt_pair(fA[dd].z, fB[dd].z);
            uint2 p3 = cvt_pair(fA[dd].w, fB[dd].w);
            uint2* vp = &Vs[kvp * 132 + dseg + 4*dd];
            *(uint4*)vp       = make_uint4(p0.x, p0.y, p1.x, p1.y);
            *(uint4*)(vp + 2) = make_uint4(p2.x, p2.y, p3.x, p3.y);
        }
        __syncthreads();

        float sacc[4][4] = {};
        #pragma unroll
        for (int nt = 0; nt < 4; nt++) {
            int krow = nt * 8 + g;
            #pragma unroll
            for (int s = 0; s < 8; s++) {
                uint2 y0 = Ks[krow * 68 + 8*s + l3];
                uint2 y1 = Ks[krow * 68 + 8*s + l3 + 4];
                uint32_t bh[2] = {y0.x, y1.x}, bl[2] = {y0.y, y1.y};
                mma_bf16(sacc[nt], qhi[s], bh);
                mma_bf16(sacc[nt], qhi[s], bl);
                mma_bf16(sacc[nt], qlo[s], bh);
            }
        }

        float cm0 = -1e30f, cm1 = -1e30f;
        #pragma unroll
        for (int nt = 0; nt < 4; nt++) {
            cm0 = fmaxf(cm0, fmaxf(sacc[nt][0], sacc[nt][1]));
            cm1 = fmaxf(cm1, fmaxf(sacc[nt][2], sacc[nt][3]));
        }
        cm0 = fmaxf(cm0, __shfl_xor_sync(0xffffffffu, cm0, 1));
        cm0 = fmaxf(cm0, __shfl_xor_sync(0xffffffffu, cm0, 2));
        cm1 = fmaxf(cm1, __shfl_xor_sync(0xffffffffu, cm1, 1));
        cm1 = fmaxf(cm1, __shfl_xor_sync(0xffffffffu, cm1, 2));
        float mn0 = fmaxf(m0_, cm0), mn1 = fmaxf(m1_, cm1);
        float sc0 = __expf(m0_ - mn0), sc1 = __expf(m1_ - mn1);
        m0_ = mn0; m1_ = mn1;

        uint32_t phi[2][4], plo[2][4];
        float rs0 = 0.f, rs1 = 0.f;
        #pragma unroll
        for (int nt = 0; nt < 4; nt++) {
            int c0 = kb + nt * 8 + 2 * l3;
            bool v0 = c0 < LP_, v1 = (c0 + 1) < LP_;
            float p00 = v0 ? __expf(sacc[nt][0] - mn0) : 0.f;
            float p01 = v1 ? __expf(sacc[nt][1] - mn0) : 0.f;
            float p10 = v0 ? __expf(sacc[nt][2] - mn1) : 0.f;
            float p11 = v1 ? __expf(sacc[nt][3] - mn1) : 0.f;
            rs0 += p00 + p01; rs1 += p10 + p11;
            uint2 hA = cvt_pair(p00, p01);
            uint2 hB = cvt_pair(p10, p11);
            int s2 = nt >> 1, o = (nt & 1) * 2;
            phi[s2][o]     = hA.x; plo[s2][o]     = hA.y;
            phi[s2][o + 1] = hB.x; plo[s2][o + 1] = hB.y;
        }
        rs0 += __shfl_xor_sync(0xffffffffu, rs0, 1);
        rs0 += __shfl_xor_sync(0xffffffffu, rs0, 2);
        rs1 += __shfl_xor_sync(0xffffffffu, rs1, 1);
        rs1 += __shfl_xor_sync(0xffffffffu, rs1, 2);
        l0_ = l0_ * sc0 + rs0;
        l1_ = l1_ * sc1 + rs1;
        #pragma unroll
        for (int dt = 0; dt < 16; dt++) {
            accO[dt][0] *= sc0; accO[dt][1] *= sc0;
            accO[dt][2] *= sc1; accO[dt][3] *= sc1;
        }

        #pragma unroll
        for (int dt = 0; dt < 16; dt++) {
            #pragma unroll
            for (int s2 = 0; s2 < 2; s2++) {
                int vr = 8 * s2 + l3;
                uint2 y0 = Vs[vr * 132 + dt * 8 + g];
                uint2 y1 = Vs[(vr + 4) * 132 + dt * 8 + g];
                uint32_t bh[2] = {y0.x, y1.x}, bl[2] = {y0.y, y1.y};
                mma_bf16(accO[dt], phi[s2], bh);
                mma_bf16(accO[dt], phi[s2], bl);
                mma_bf16(accO[dt], plo[s2], bh);
            }
        }
    }

    float* AVp = half ? AV1 : AV0;
    float* Mo  = half ? M1 : M0;
    float* Lo  = half ? L1 : L0;
    #pragma unroll
    for (int dt = 0; dt < 16; dt++) {
        int c = dt * 8 + 2 * l3;
        if (r0 < LP_)
            *(float2*)(AVp + ((ll)b * LP_ + r0) * 128 + c) =
                make_float2(accO[dt][0], accO[dt][1]);
        if (r1 < LP_)
            *(float2*)(AVp + ((ll)b * LP_ + r1) * 128 + c) =
                make_float2(accO[dt][2], accO[dt][3]);
    }
    if (l3 == 0) {
        if (r0 < LP_) { Mo[(ll)b * LP_ + r0] = m0_; Lo[(ll)b * LP_ + r0] = l0_; }
        if (r1 < LP_) { Mo[(ll)b * LP_ + r1] = m1_; Lo[(ll)b * LP_ + r1] = l1_; }
    }
}

// ---------------- prep_all: repacks + bq + Wq0 GEMM + Chl GEMM ----------------
// grid (32, 7): y=0..3 repack wk/wv/wo/jp, y=4 bq, y=5 Wq0 (x<5), y=6 Chl (x<8)
__global__ void __launch_bounds__(256)
prep_all(const float* wq_w, const float* wk_w, const float* wv_w,
         const float* wo_w, const float* jp_w, const float* jc_w,
         uint2* wkp, uint2* wvp, uint2* wop, uint2* jpp,
         const float* emb_b, const float* wq_b, float* bq,
         const float* emb_w, float* Wq0,
         const float* cf, const float* jc_b, uint2* Chl)
{
    __shared__ __align__(16) uint2 As[2 * 64 * 12];
    __shared__ __align__(16) uint2 Bs[2 * 8 * 132];
    int y = blockIdx.y;
    if (y == 5) {
        if (blockIdx.x >= 5) return;
        gemm_body<0, 1, 0>(emb_w, nullptr, nullptr, nullptr, nullptr, nullptr,
            nullptr, wq_w, nullptr, Wq0, nullptr,
            E_, D_, D_, D_, D_, 1.f, blockIdx.x * 64, As, Bs);
        return;
    }
    if (y == 6) {
        if (blockIdx.x >= 8) return;
        gemm_body<1, 1, 1>(cf, nullptr, nullptr, nullptr, nullptr, nullptr,
            nullptr, jc_w, jc_b, nullptr, Chl,
            B_*NC_, D_, D_, D_, D_, 1.f, blockIdx.x * 64, As, Bs);
        return;
    }
    if (y == 4) {
        if (blockIdx.x == 0 && threadIdx.x < 128) {
            int n = threadIdx.x;
            float s = wq_b[n];
            for (int k = 0; k < D_; k++) s = fmaf(emb_b[k], wq_w[k * D_ + n], s);
            bq[n] = s;
        }
        return;
    }
    int i = blockIdx.x * 256 + threadIdx.x;
    const float* s; uint2* d;
    switch (y) {
        case 0: s = wk_w; d = wkp; break;
        case 1: s = wv_w; d = wvp; break;
        case 2: s = wo_w; d = wop; break;
        default: s = jp_w; d = jpp; break;
    }
    int kp = i >> 7, n = i & 127;
    d[i] = cvt_pair(s[(2 * kp) * D_ + n], s[(2 * kp + 1) * D_ + n]);
}

__global__ void __launch_bounds__(256, 2)
gemm_qkv(const float* __restrict__ in_pe, const float* __restrict__ Wq0,
         const float* __restrict__ bq, uint2* __restrict__ Qhl,
         const float* __restrict__ in_pfx,
         const uint2* __restrict__ wkp, const float* __restrict__ wk_b,
         uint2* __restrict__ Khl,
         const uint2* __restrict__ wvp, const float* __restrict__ wv_b,
         float* __restrict__ Vf, float inv_sqrt_d)
{
    __shared__ __align__(16) uint2 As[2 * 64 * 12];
    __shared__ __align__(16) uint2 Bs[2 * 8 * 132];
    int m0 = blockIdx.y * 64;
    if (blockIdx.z == 0)
        gemm_body<0, 1, 1>(in_pe, nullptr, nullptr, nullptr, nullptr, nullptr,
            nullptr, Wq0, bq, nullptr, Qhl,
            B_*LP_, D_, E_, E_, D_, inv_sqrt_d, m0, As, Bs);
    else if (blockIdx.z == 1)
        gemm_body<0, 0, 1>(in_pfx, nullptr, nullptr, nullptr, nullptr, nullptr,
            wkp, nullptr, wk_b, nullptr, Khl,
            B_*LP_, D_, D_, D_, D_, 1.f, m0, As, Bs);
    else
        gemm_body<0, 0, 0>(in_pfx, nullptr, nullptr, nullptr, nullptr, nullptr,
            wvp, nullptr, wv_b, Vf, nullptr,
            B_*LP_, D_, D_, D_, D_, 1.f, m0, As, Bs);
}

// pf = combine(AV0,AV1;m,l) @ wo + b
__global__ void __launch_bounds__(256, 2)
gemm_wo(const float* __restrict__ AV0, const float* __restrict__ AV1,
        const float* __restrict__ M0, const float* __restrict__ L0,
        const float* __restrict__ M1, const float* __restrict__ L1,
        const uint2* __restrict__ wop, const float* __restrict__ wo_b,
        float* __restrict__ pf)
{
    __shared__ __align__(16) uint2 As[2 * 64 * 12];
    __shared__ __align__(16) uint2 Bs[2 * 8 * 132];
    gemm_body<4, 0, 0>(AV0, AV1, M0, L0, M1, L1,
        wop, nullptr, wo_b, pf, nullptr,
        B_*LP_, D_, D_, D_, D_, 1.f, blockIdx.y * 64, As, Bs);
}

// P = relu(pf) @ jp + b  (Chl lives in prep_all now)
__global__ void __launch_bounds__(256, 2)
gemm_pc(const float* __restrict__ pf, const uint2* __restrict__ jpp,
        const float* __restrict__ jp_b, float* __restrict__ P)
{
    __shared__ __align__(16) uint2 As[2 * 64 * 12];
    __shared__ __align__(16) uint2 Bs[2 * 8 * 132];
    gemm_body<1, 0, 0>(pf, nullptr, nullptr, nullptr, nullptr, nullptr,
        jpp, nullptr, jp_b, P, nullptr,
        B_*LP_, D_, D_, D_, D_, 1.f, blockIdx.y * 64, As, Bs);
}

// ---------------- A-logits: bf16x3 64x64 GEMM + sigmoid + partial sums -------
__global__ void __launch_bounds__(256, 2)
alogits_kernel(const float* __restrict__ Pm, const uint2* __restrict__ Chl,
               float* __restrict__ Aout, float* __restrict__ Apart)
{
    __shared__ __align__(16) uint2 As[2][768];
    __shared__ __align__(16) uint2 Bs[2][768];
    __shared__ float red[256];

    int b = blockIdx.y, mt = blockIdx.x, m0 = mt * 64;
    const float* A = Pm + (ll)b * LP_ * D_;
    const uint2* Bh = Chl + (ll)b * NC_ * 64;
    float* C = Aout + (ll)b * LP_ * NC_;
    int t = threadIdx.x, warp = t >> 5, lane = t & 31;
    int g = lane >> 2, l3 = lane & 3;
    int wm = (warp & 1) * 32, wn = (warp >> 1) * 16;

    float acc[2][2][4] = {};
    int ar = t >> 2, akf = (t & 3) * 4, akp = (t & 3) * 2;
    uint4 ua, ub;

    auto loadAB = [&](int k0) {
        int gm = m0 + ar;
        float4 rv = make_float4(0.f, 0.f, 0.f, 0.f);
        if (gm < LP_) rv = *(const float4*)(A + (ll)gm * D_ + k0 + akf);
        uint2 p0 = cvt_pair(rv.x, rv.y), p1 = cvt_pair(rv.z, rv.w);
        ua = make_uint4(p0.x, p0.y, p1.x, p1.y);
        ub = *(const uint4*)(Bh + (ll)ar * 64 + (k0 >> 1) + akp);
    };
    auto storeAB = [&](int s) {
        *(uint4*)&As[s][ar * 12 + akp] = ua;
        *(uint4*)&Bs[s][ar * 12 + akp] = ub;
    };
    loadAB(0); storeAB(0);
    __syncthreads();

    for (int it = 0; it < 8; it++) {
        int s = it & 1;
        if (it < 7) loadAB((it + 1) << 4);
        uint32_t ahi[2][4], alo[2][4];
        #pragma unroll
        for (int mi = 0; mi < 2; mi++) {
            int rr = wm + mi * 16 + g;
            uint2 x0 = As[s][rr * 12 + l3];
            uint2 x1 = As[s][(rr + 8) * 12 + l3];
            uint2 x2 = As[s][rr * 12 + l3 + 4];
            uint2 x3 = As[s][(rr + 8) * 12 + l3 + 4];
            ahi[mi][0] = x0.x; alo[mi][0] = x0.y;
            ahi[mi][1] = x1.x; alo[mi][1] = x1.y;
            ahi[mi][2] = x2.x; alo[mi][2] = x2.y;
            ahi[mi][3] = x3.x; alo[mi][3] = x3.y;
        }
        uint32_t bhi[2][2], blo[2][2];
        #pragma unroll
        for (int ni = 0; ni < 2; ni++) {
            int cc = wn + ni * 8 + g;
            uint2 y0 = Bs[s][cc * 12 + l3];
            uint2 y1 = Bs[s][cc * 12 + l3 + 4];
            bhi[ni][0] = y0.x; blo[ni][0] = y0.y;
            bhi[ni][1] = y1.x; blo[ni][1] = y1.y;
        }
        #pragma unroll
        for (int mi = 0; mi < 2; mi++)
            #pragma unroll
            for (int ni = 0; ni < 2; ni++) {
                mma_bf16(acc[mi][ni], ahi[mi], bhi[ni]);
                mma_bf16(acc[mi][ni], ahi[mi], blo[ni]);
                mma_bf16(acc[mi][ni], alo[mi], bhi[ni]);
            }
        if (it < 7) storeAB(s ^ 1);
        __syncthreads();
    }

    float tsum = 0.f;
    #pragma unroll
    for (int mi = 0; mi < 2; mi++)
        #pragma unroll
        for (int ni = 0; ni < 2; ni++) {
            int r0 = m0 + wm + mi * 16 + g;
            int c0 = wn + ni * 8 + 2 * l3;
            if (r0 < LP_) {
                float v0 = 1.f / (1.f + __expf(-acc[mi][ni][0]));
                float v1 = 1.f / (1.f + __expf(-acc[mi][ni][1]));
                *(float2*)(C + (ll)r0 * NC_ + c0) = make_float2(v0, v1);
                tsum += v0 + v1;
            }
            if (r0 + 8 < LP_) {
                float v0 = 1.f / (1.f + __expf(-acc[mi][ni][2]));
                float v1 = 1.f / (1.f + __expf(-acc[mi][ni][3]));
                *(float2*)(C + (ll)(r0 + 8) * NC_ + c0) = make_float2(v0, v1);
                tsum += v0 + v1;
            }
        }
    red[t] = tsum; __syncthreads();
    for (int s2 = 128; s2 > 0; s2 >>= 1) {
        if (t < s2) red[t] += red[t + s2];
        __syncthreads();
    }
    if (t == 0) Apart[b * 16 + mt] = red[0];
}

// ---------------- tanh outer-product weighted reduction ---------------------
__global__ void tanh_outer_kernel(const float* __restrict__ pf,
                                  const float* __restrict__ cf,
                                  const float* __restrict__ A,
                                  float* __restrict__ part)
{
    int b = blockIdx.y, tile = blockIdx.x;
    int d = threadIdx.x;  // 128
    __shared__ float cfs[NC_ * D_];
    for (int i = threadIdx.x; i < NC_ * D_; i += 128)
        cfs[i] = cf[(ll)b * NC_ * D_ + i];
    __syncthreads();
    float acc = 0.f;
    int i0 = tile * ITILE_;
    for (int i = i0; i < i0 + ITILE_; i++) {
        float pv = pf[((ll)b * LP_ + i) * D_ + d];
        const float* Ar = A + ((ll)b * LP_ + i) * NC_;
        #pragma unroll 4
        for (int k = 0; k < NC_; k++) {
            float w = Ar[k];
            float x = pv * cfs[k * D_ + d];
            float th;
            asm("tanh.approx.f32 %0, %1;" : "=f"(th) : "f"(x));
            acc = fmaf(th, w, acc);
        }
    }
    part[((ll)b * NTILE_ + tile) * D_ + d] = acc;
}

__global__ void cp_reduce_kernel(const float* __restrict__ part,
                                 const float* __restrict__ Apart,
                                 float* __restrict__ cp)
{
    int b = blockIdx.x;
    int d = threadIdx.x;  // 128
    float as = 0.f;
    #pragma unroll
    for (int j = 0; j < 16; j++) as += Apart[b * 16 + j];
    float s = 0.f;
    for (int t2 = 0; t2 < NTILE_; t2++)
        s += part[((ll)b * NTILE_ + t2) * D_ + d];
    cp[b * D_ + d] = s / as;
}

// ---------------- skinny GEMM (M = 8 rows) -----------------------------------
template<bool RELU_OUT>
__global__ void __launch_bounds__(256)
skinny_gemm(const float* __restrict__ A, const float* __restrict__ W,
            const float* __restrict__ bias, float* __restrict__ C,
            int N, int K)
{
    __shared__ float As[8 * 1024];
    __shared__ float red[8][8][32];
    int t = threadIdx.x;
    for (int i = t; i < 8 * K; i += 256) As[i] = A[i];
    __syncthreads();
    int n = blockIdx.x * 32 + (t & 31);
    int ks = t >> 5;
    int kseg = K >> 3;
    float acc[8] = {};
    if (n < N) {
        for (int k = ks * kseg; k < (ks + 1) * kseg; k++) {
            float w = W[(ll)k * N + n];
            #pragma unroll
            for (int m = 0; m < 8; m++) acc[m] = fmaf(As[m * K + k], w, acc[m]);
        }
    }
    #pragma unroll
    for (int m = 0; m < 8; m++) red[ks][m][t & 31] = acc[m];
    __syncthreads();
    int m = t >> 5, lnn = t & 31;
    int nn = blockIdx.x * 32 + lnn;
    if (nn < N) {
        float s = 0.f;
        #pragma unroll
        for (int j = 0; j < 8; j++) s += red[j][m][lnn];
        s += bias[nn];
        if (RELU_OUT) s = fmaxf(s, 0.f);
        C[(ll)m * N + nn] = s;
    }
}

// ---------------- launch ------------------------------------------------------
extern "C" void kernel_launch(void* const* d_in, const int* in_sizes, int n_in,
                              void* d_out, int out_size)
{
    const float* in_pe  = (const float*)d_in[0];
    const float* in_pfx = (const float*)d_in[1];
    const float* in_cf  = (const float*)d_in[2];
    const float* emb_w = (const float*)d_in[3];  const float* emb_b = (const float*)d_in[4];
    const float* wq_w  = (const float*)d_in[5];  const float* wq_b  = (const float*)d_in[6];
    const float* wk_w  = (const float*)d_in[7];  const float* wk_b  = (const float*)d_in[8];
    const float* wv_w  = (const float*)d_in[9];  const float* wv_b  = (const float*)d_in[10];
    const float* wo_w  = (const float*)d_in[11]; const float* wo_b  = (const float*)d_in[12];
    const float* jp_w  = (const float*)d_in[13]; const float* jp_b  = (const float*)d_in[14];
    const float* jc_w  = (const float*)d_in[15]; const float* jc_b  = (const float*)d_in[16];
    const float* c1_w  = (const float*)d_in[17]; const float* c1_b  = (const float*)d_in[18];
    const float* c2_w  = (const float*)d_in[19]; const float* c2_b  = (const float*)d_in[20];
    const float* c3_w  = (const float*)d_in[21]; const float* c3_b  = (const float*)d_in[22];
    const float* c4_w  = (const float*)d_in[23]; const float* c4_b  = (const float*)d_in[24];

    uint2 *Qhl, *Khl, *Chl, *wkp, *wvp, *wop, *jpp;
    float *Wq0, *Vf, *AV0, *AV1, *M0, *L0, *M1, *L1, *pf, *P, *A, *bq, *Apart,
          *part, *cp, *h1, *h2, *h3;
    cudaGetSymbolAddress((void**)&Qhl,  g_Qhl);
    cudaGetSymbolAddress((void**)&Khl,  g_Khl);
    cudaGetSymbolAddress((void**)&Chl,  g_Chl);
    cudaGetSymbolAddress((void**)&wkp,  g_wkp);
    cudaGetSymbolAddress((void**)&wvp,  g_wvp);
    cudaGetSymbolAddress((void**)&wop,  g_wop);
    cudaGetSymbolAddress((void**)&jpp,  g_jpp);
    cudaGetSymbolAddress((void**)&Wq0,  g_Wq0);
    cudaGetSymbolAddress((void**)&Vf,   g_Vf);
    cudaGetSymbolAddress((void**)&AV0,  g_AV0);
    cudaGetSymbolAddress((void**)&AV1,  g_AV1);
    cudaGetSymbolAddress((void**)&M0,   g_M0);
    cudaGetSymbolAddress((void**)&L0,   g_L0);
    cudaGetSymbolAddress((void**)&M1,   g_M1);
    cudaGetSymbolAddress((void**)&L1,   g_L1);
    cudaGetSymbolAddress((void**)&pf,   g_pf);
    cudaGetSymbolAddress((void**)&P,    g_P);
    cudaGetSymbolAddress((void**)&A,    g_A);
    cudaGetSymbolAddress((void**)&bq,   g_bq);
    cudaGetSymbolAddress((void**)&Apart,g_Apart);
    cudaGetSymbolAddress((void**)&part, g_part);
    cudaGetSymbolAddress((void**)&cp,   g_cp);
    cudaGetSymbolAddress((void**)&h1,   g_h1);
    cudaGetSymbolAddress((void**)&h2,   g_h2);
    cudaGetSymbolAddress((void**)&h3,   g_h3);

    const float inv_sqrt_d = 0.088388347648318440550f;  // 1/sqrt(128)

    // 0. prep: 4 weight repacks + bq + Wq0 GEMM + Chl GEMM (one launch)
    prep_all<<<dim3(32,7),256>>>(wq_w, wk_w, wv_w, wo_w, jp_w, jc_w,
                                 wkp, wvp, wop, jpp,
                                 emb_b, wq_b, bq, emb_w, Wq0,
                                 in_cf, jc_b, Chl);
    // 1. Q/K/V
    gemm_qkv<<<dim3(1,125,3),256>>>(in_pe, Wq0, bq, Qhl,
                                    in_pfx, wkp, wk_b, Khl,
                                    wvp, wv_b, Vf, inv_sqrt_d);
    // 2. split-KV flash attention -> partial O + (m,l)
    flash_attn<<<dim3(16,2,B_),128>>>(Qhl, Khl, Vf, AV0, AV1, M0, L0, M1, L1);
    // 3. pf = combine(AV partials) @ wo + b
    gemm_wo<<<dim3(1,125),256>>>(AV0, AV1, M0, L0, M1, L1, wop, wo_b, pf);
    // 4. P
    gemm_pc<<<dim3(1,125),256>>>(pf, jpp, jp_b, P);
    // 5. A = sigmoid(P @ C^T) + partial sums
    alogits_kernel<<<dim3(16,B_),256>>>(P, Chl, A, Apart);
    // 6. tanh outer product partials
    tanh_outer_kernel<<<dim3(NTILE_,B_),128>>>(pf, in_cf, A, part);
    // 7. reduce + normalize
    cp_reduce_kernel<<<B_,128>>>(part, Apart, cp);
    // 8-11. classifier MLP
    skinny_gemm<true ><<<32,256>>>(cp, c1_w, c1_b, h1, 1024, D_);
    skinny_gemm<true ><<<32,256>>>(h1, c2_w, c2_b, h2, 1024, 1024);
    skinny_gemm<true ><<<8, 256>>>(h2, c3_w, c3_b, h3, 256, 1024);
    skinny_gemm<false><<<1, 256>>>(h3, c4_w, c4_b, (float*)d_out, 1, 256);
}

// round 15
// speedup vs baseline: 1.1440x; 1.0234x over previous
#include <cuda_runtime.h>
#include <math.h>
#include <stdint.h>

#define B_  8
#define LP_ 1000
#define NC_ 64
#define D_  128
#define E_  320
#define NTILE_ 100
#define ITILE_ 10
typedef long long ll;

// ---------------- scratch (device globals) ----------------------------------
__device__ __align__(16) uint2 g_Qhl[B_*LP_*64];
__device__ __align__(16) uint2 g_Khl[B_*LP_*64];
__device__ __align__(16) uint2 g_Chl[B_*NC_*64];
__device__ __align__(16) uint2 g_wkp[64*D_];
__device__ __align__(16) uint2 g_wvp[64*D_];
__device__ __align__(16) uint2 g_wop[64*D_];
__device__ __align__(16) uint2 g_jpp[64*D_];
__device__ __align__(16) float g_Wq0[E_*D_];
__device__ __align__(16) float g_Vf [B_*LP_*D_];
__device__ __align__(16) float g_AV0[B_*LP_*D_];
__device__ __align__(16) float g_AV1[B_*LP_*D_];
__device__ __align__(16) float g_M0 [B_*LP_];
__device__ __align__(16) float g_L0 [B_*LP_];
__device__ __align__(16) float g_M1 [B_*LP_];
__device__ __align__(16) float g_L1 [B_*LP_];
__device__ __align__(16) float g_pf [B_*LP_*D_];
__device__ __align__(16) float g_P  [B_*LP_*D_];
__device__ __align__(16) float g_A  [B_*LP_*NC_];
__device__ __align__(16) float g_bq [D_];
__device__ __align__(16) float g_Apart[B_*16];
__device__ __align__(16) float g_part[B_*NTILE_*D_];
__device__ __align__(16) float g_cp [B_*D_];
__device__ __align__(16) float g_h1 [B_*1024];
__device__ __align__(16) float g_h2 [B_*1024];
__device__ __align__(16) float g_h3 [B_*256];

// ---------------- bf16 helpers -----------------------------------------------
__device__ __forceinline__ uint32_t packbf(float x, float y) {  // lo=x, hi=y
    uint32_t r;
    asm("cvt.rn.bf16x2.f32 %0, %1, %2;" : "=r"(r) : "f"(y), "f"(x));
    return r;
}
__device__ __forceinline__ float lowbf(uint32_t h)  { return __uint_as_float(h << 16); }
__device__ __forceinline__ float highbf(uint32_t h) { return __uint_as_float(h & 0xFFFF0000u); }
__device__ __forceinline__ uint2 cvt_pair(float x, float y) {
    uint32_t h = packbf(x, y);
    uint32_t l = packbf(x - lowbf(h), y - highbf(h));
    return make_uint2(h, l);
}
__device__ __forceinline__ void mma_bf16(float* d, const uint32_t* a, const uint32_t* b) {
    asm volatile(
        "mma.sync.aligned.m16n8k16.row.col.f32.bf16.bf16.f32 "
        "{%0,%1,%2,%3}, {%4,%5,%6,%7}, {%8,%9}, {%0,%1,%2,%3};\n"
        : "+f"(d[0]), "+f"(d[1]), "+f"(d[2]), "+f"(d[3])
        : "r"(a[0]), "r"(a[1]), "r"(a[2]), "r"(a[3]), "r"(b[0]), "r"(b[1]));
}

// ---------------- unified GEMM body: 64(M) x 128(N) tile, BK=16, bf16x3 -----
// AMODE: 0=A fp32, 1=fp32+relu, 4=flash-combine(Af,Af2+M/L)
// BMODE: 0=pre-paired uint2 [kp][n], 1=fp32 K-major pack-on-fly
// EPI: 0=fp32 out, 1=pair uint2 out, 2=fp32 out + relu-pairs to smem (pitch 68).
template<int AMODE, int BMODE, int EPI>
__device__ __forceinline__ void gemm_body(
    const float* __restrict__ Af, const float* __restrict__ Af2,
    const float* __restrict__ M0p, const float* __restrict__ L0p,
    const float* __restrict__ M1p, const float* __restrict__ L1p,
    const uint2* __restrict__ Bh, const float* __restrict__ Bf,
    const float* __restrict__ bias, float* __restrict__ Cf, uint2* Ch,
    int M, int N, int K, int lda, int ldb,
    float alpha, int m0, uint2* As, uint2* Bs)
{
    constexpr int ASN = 64 * 12;
    constexpr int BSN = 8 * 132;

    int t = threadIdx.x, warp = t >> 5, lane = t & 31;
    int g = lane >> 2, l3 = lane & 3;
    int wm = (warp & 1) * 32, wn = (warp >> 1) * 32;

    float acc[2][4][4] = {};

    int ar = t >> 2, akf = (t & 3) * 4, akp = (t & 3) * 2;
    int bk = t >> 5, bn = (t & 31) * 4;

    int kt = K >> 4;
    uint4 ua, ub0, ub1;

    auto loadA = [&](int k0) {
        int gm = m0 + ar;
        float4 rv = make_float4(0.f, 0.f, 0.f, 0.f);
        if (gm < M) {
            int gk = k0 + akf;
            rv = *(const float4*)(Af + (ll)gm * lda + gk);
            if (AMODE == 4) {
                float4 r2 = *(const float4*)(Af2 + (ll)gm * lda + gk);
                float m0v = M0p[gm], m1v = M1p[gm];
                float mm = fmaxf(m0v, m1v);
                float a0 = __expf(m0v - mm), a1 = __expf(m1v - mm);
                float inv = 1.f / (a0 * L0p[gm] + a1 * L1p[gm]);
                rv.x = (rv.x * a0 + r2.x * a1) * inv;
                rv.y = (rv.y * a0 + r2.y * a1) * inv;
                rv.z = (rv.z * a0 + r2.z * a1) * inv;
                rv.w = (rv.w * a0 + r2.w * a1) * inv;
            }
            if (AMODE == 1) {
                rv.x = fmaxf(rv.x, 0.f); rv.y = fmaxf(rv.y, 0.f);
                rv.z = fmaxf(rv.z, 0.f); rv.w = fmaxf(rv.w, 0.f);
            }
        }
        uint2 p0 = cvt_pair(rv.x, rv.y), p1 = cvt_pair(rv.z, rv.w);
        ua = make_uint4(p0.x, p0.y, p1.x, p1.y);
    };
    auto loadB = [&](int k0) {
        if (BMODE == 0) {
            const uint2* p = Bh + (ll)((k0 >> 1) + bk) * N + bn;
            ub0 = *(const uint4*)p;
            ub1 = *(const uint4*)(p + 2);
        } else {
            int gk0 = k0 + 2 * bk, gk1 = gk0 + 1;
            float4 r0 = *(const float4*)(Bf + (ll)gk0 * ldb + bn);
            float4 r1 = *(const float4*)(Bf + (ll)gk1 * ldb + bn);
            uint2 q0 = cvt_pair(r0.x, r1.x), q1 = cvt_pair(r0.y, r1.y);
            uint2 q2 = cvt_pair(r0.z, r1.z), q3 = cvt_pair(r0.w, r1.w);
            ub0 = make_uint4(q0.x, q0.y, q1.x, q1.y);
            ub1 = make_uint4(q2.x, q2.y, q3.x, q3.y);
        }
    };
    auto storeA = [&](int s) { *(uint4*)&As[s * ASN + ar * 12 + akp] = ua; };
    auto storeB = [&](int s) {
        *(uint4*)&Bs[s * BSN + bk * 132 + bn]     = ub0;
        *(uint4*)&Bs[s * BSN + bk * 132 + bn + 2] = ub1;
    };

    loadA(0); loadB(0);
    storeA(0); storeB(0);
    __syncthreads();

    for (int it = 0; it < kt; it++) {
        int s = it & 1;
        if (it + 1 < kt) { loadA((it + 1) << 4); loadB((it + 1) << 4); }

        uint32_t ahi[2][4], alo[2][4];
        #pragma unroll
        for (int mi = 0; mi < 2; mi++) {
            int rr = wm + mi * 16 + g;
            uint2 x0 = As[s * ASN + rr * 12 + l3];
            uint2 x1 = As[s * ASN + (rr + 8) * 12 + l3];
            uint2 x2 = As[s * ASN + rr * 12 + l3 + 4];
            uint2 x3 = As[s * ASN + (rr + 8) * 12 + l3 + 4];
            ahi[mi][0] = x0.x; alo[mi][0] = x0.y;
            ahi[mi][1] = x1.x; alo[mi][1] = x1.y;
            ahi[mi][2] = x2.x; alo[mi][2] = x2.y;
            ahi[mi][3] = x3.x; alo[mi][3] = x3.y;
        }
        uint32_t bhi[4][2], blo[4][2];
        #pragma unroll
        for (int ni = 0; ni < 4; ni++) {
            int cc = wn + ni * 8 + g;
            uint2 y0 = Bs[s * BSN + l3 * 132 + cc];
            uint2 y1 = Bs[s * BSN + (l3 + 4) * 132 + cc];
            bhi[ni][0] = y0.x; blo[ni][0] = y0.y;
            bhi[ni][1] = y1.x; blo[ni][1] = y1.y;
        }
        #pragma unroll
        for (int mi = 0; mi < 2; mi++)
            #pragma unroll
            for (int ni = 0; ni < 4; ni++) {
                mma_bf16(acc[mi][ni], ahi[mi], bhi[ni]);
                mma_bf16(acc[mi][ni], ahi[mi], blo[ni]);
                mma_bf16(acc[mi][ni], alo[mi], bhi[ni]);
            }
        if (it + 1 < kt) { storeA(s ^ 1); storeB(s ^ 1); }
        __syncthreads();
    }

    #pragma unroll
    for (int mi = 0; mi < 2; mi++)
        #pragma unroll
        for (int ni = 0; ni < 4; ni++) {
            int r0 = m0 + wm + mi * 16 + g;
            int c0 = wn + ni * 8 + 2 * l3;
            float b0 = 0.f, b1 = 0.f;
            if (bias) { b0 = bias[c0]; b1 = bias[c0 + 1]; }
            float v00 = (acc[mi][ni][0] + b0) * alpha;
            float v01 = (acc[mi][ni][1] + b1) * alpha;
            float v10 = (acc[mi][ni][2] + b0) * alpha;
            float v11 = (acc[mi][ni][3] + b1) * alpha;
            if (EPI == 0) {
                if (r0 < M)     *(float2*)(Cf + (ll)r0 * N + c0)       = make_float2(v00, v01);
                if (r0 + 8 < M) *(float2*)(Cf + (ll)(r0 + 8) * N + c0) = make_float2(v10, v11);
            } else if (EPI == 1) {
                if (r0 < M)     Ch[(ll)r0 * (N >> 1) + (c0 >> 1)]       = cvt_pair(v00, v01);
                if (r0 + 8 < M) Ch[(ll)(r0 + 8) * (N >> 1) + (c0 >> 1)] = cvt_pair(v10, v11);
            } else {  // EPI 2: fp32 out + relu-pairs into smem (pitch 68)
                int lr = wm + mi * 16 + g;
                *(float2*)(Cf + (ll)r0 * N + c0)       = make_float2(v00, v01);
                *(float2*)(Cf + (ll)(r0 + 8) * N + c0) = make_float2(v10, v11);
                Ch[lr * 68 + (c0 >> 1)]       = cvt_pair(fmaxf(v00, 0.f), fmaxf(v01, 0.f));
                Ch[(lr + 8) * 68 + (c0 >> 1)] = cvt_pair(fmaxf(v10, 0.f), fmaxf(v11, 0.f));
            }
        }
}

// ---------------- flash attention (split-KV): partial O + (m,l) --------------
__global__ void __launch_bounds__(128)
flash_attn(const uint2* __restrict__ Qhl, const uint2* __restrict__ Khl,
           const float* __restrict__ Vf,
           float* __restrict__ AV0, float* __restrict__ AV1,
           float* __restrict__ M0, float* __restrict__ L0,
           float* __restrict__ M1, float* __restrict__ L1)
{
    __shared__ __align__(16) uint2 Ks[32 * 68];
    __shared__ __align__(16) uint2 Vs[16 * 132];

    int b = blockIdx.z, half = blockIdx.y, m0t = blockIdx.x * 64;
    int kvOff = half * 512;
    int t = threadIdx.x, w = t >> 5, lane = t & 31;
    int g = lane >> 2, l3 = lane & 3;
    int r0 = m0t + w * 16 + g, r1 = r0 + 8;

    uint32_t qhi[8][4], qlo[8][4];
    {
        const uint2* Q0 = Qhl + ((ll)b * LP_ + r0) * 64;
        const uint2* Q1 = Qhl + ((ll)b * LP_ + r1) * 64;
        #pragma unroll
        for (int s = 0; s < 8; s++) {
            uint2 u0 = make_uint2(0u,0u), u2 = u0, u1 = u0, u3 = u0;
            if (r0 < LP_) { u0 = Q0[8*s + l3]; u2 = Q0[8*s + l3 + 4]; }
            if (r1 < LP_) { u1 = Q1[8*s + l3]; u3 = Q1[8*s + l3 + 4]; }
            qhi[s][0] = u0.x; qlo[s][0] = u0.y;
            qhi[s][1] = u1.x; qlo[s][1] = u1.y;
            qhi[s][2] = u2.x; qlo[s][2] = u2.y;
            qhi[s][3] = u3.x; qlo[s][3] = u3.y;
        }
    }

    float accO[16][4] = {};
    float m0_ = -1e30f, m1_ = -1e30f, l0_ = 0.f, l1_ = 0.f;

    int kvp = t >> 3, dseg = (t & 7) * 16;

    for (int iter = 0; iter < 16; iter++) {
        int kb = kvOff + iter * 32;
        uint4 kreg[8];
        #pragma unroll
        for (int j = 0; j < 8; j++) {
            int idx = t + 128 * j, row = idx >> 5, q4 = idx & 31;
            int gkv = kb + row;
            kreg[j] = (gkv < LP_)
                ? *(const uint4*)(Khl + ((ll)b * LP_ + gkv) * 64 + q4 * 2)
                : make_uint4(0u,0u,0u,0u);
        }
        float4 fA[4], fB[4];
        {
            int rA = kb + 2 * kvp, rB = rA + 1;
            #pragma unroll
            for (int dd = 0; dd < 4; dd++) {
                fA[dd] = (rA < LP_) ? *(const float4*)(Vf + ((ll)b * LP_ + rA) * 128 + dseg + 4*dd)
                                    : make_float4(0.f,0.f,0.f,0.f);
                fB[dd] = (rB < LP_) ? *(const float4*)(Vf + ((ll)b * LP_ + rB) * 128 + dseg + 4*dd)
                                    : make_float4(0.f,0.f,0.f,0.f);
            }
        }
        __syncthreads();
        #pragma unroll
        for (int j = 0; j < 8; j++) {
            int idx = t + 128 * j, row = idx >> 5, q4 = idx & 31;
            *(uint4*)&Ks[row * 68 + q4 * 2] = kreg[j];
        }
        #pragma unroll
        for (int dd = 0; dd < 4; dd++) {
            uint2 p0 = cvt_pair(fA[dd].x, fB[dd].x);
            uint2 p1 = cvt_pair(fA[dd].y, fB[dd].y);
            uint2 p2 = cvt_pair(fA[dd].z, fB[dd].z);
            uint2 p3 = cvt_pair(fA[dd].w, fB[dd].w);
            uint2* vp = &Vs[kvp * 132 + dseg + 4*dd];
            *(uint4*)vp       = make_uint4(p0.x, p0.y, p1.x, p1.y);
            *(uint4*)(vp + 2) = make_uint4(p2.x, p2.y, p3.x, p3.y);
        }
        __syncthreads();

        float sacc[4][4] = {};
        #pragma unroll
        for (int nt = 0; nt < 4; nt++) {
            int krow = nt * 8 + g;
            #pragma unroll
            for (int s = 0; s < 8; s++) {
                uint2 y0 = Ks[krow * 68 + 8*s + l3];
                uint2 y1 = Ks[krow * 68 + 8*s + l3 + 4];
                uint32_t bh[2] = {y0.x, y1.x}, bl[2] = {y0.y, y1.y};
                mma_bf16(sacc[nt], qhi[s], bh);
                mma_bf16(sacc[nt], qhi[s], bl);
                mma_bf16(sacc[nt], qlo[s], bh);
            }
        }

        float cm0 = -1e30f, cm1 = -1e30f;
        #pragma unroll
        for (int nt = 0; nt < 4; nt++) {
            cm0 = fmaxf(cm0, fmaxf(sacc[nt][0], sacc[nt][1]));
            cm1 = fmaxf(cm1, fmaxf(sacc[nt][2], sacc[nt][3]));
        }
        cm0 = fmaxf(cm0, __shfl_xor_sync(0xffffffffu, cm0, 1));
        cm0 = fmaxf(cm0, __shfl_xor_sync(0xffffffffu, cm0, 2));
        cm1 = fmaxf(cm1, __shfl_xor_sync(0xffffffffu, cm1, 1));
        cm1 = fmaxf(cm1, __shfl_xor_sync(0xffffffffu, cm1, 2));
        float mn0 = fmaxf(m0_, cm0), mn1 = fmaxf(m1_, cm1);
        float sc0 = __expf(m0_ - mn0), sc1 = __expf(m1_ - mn1);
        m0_ = mn0; m1_ = mn1;

        uint32_t phi[2][4], plo[2][4];
        float rs0 = 0.f, rs1 = 0.f;
        #pragma unroll
        for (int nt = 0; nt < 4; nt++) {
            int c0 = kb + nt * 8 + 2 * l3;
            bool v0 = c0 < LP_, v1 = (c0 + 1) < LP_;
            float p00 = v0 ? __expf(sacc[nt][0] - mn0) : 0.f;
            float p01 = v1 ? __expf(sacc[nt][1] - mn0) : 0.f;
            float p10 = v0 ? __expf(sacc[nt][2] - mn1) : 0.f;
            float p11 = v1 ? __expf(sacc[nt][3] - mn1) : 0.f;
            rs0 += p00 + p01; rs1 += p10 + p11;
            uint2 hA = cvt_pair(p00, p01);
            uint2 hB = cvt_pair(p10, p11);
            int s2 = nt >> 1, o = (nt & 1) * 2;
            phi[s2][o]     = hA.x; plo[s2][o]     = hA.y;
            phi[s2][o + 1] = hB.x; plo[s2][o + 1] = hB.y;
        }
        rs0 += __shfl_xor_sync(0xffffffffu, rs0, 1);
        rs0 += __shfl_xor_sync(0xffffffffu, rs0, 2);
        rs1 += __shfl_xor_sync(0xffffffffu, rs1, 1);
        rs1 += __shfl_xor_sync(0xffffffffu, rs1, 2);
        l0_ = l0_ * sc0 + rs0;
        l1_ = l1_ * sc1 + rs1;
        #pragma unroll
        for (int dt = 0; dt < 16; dt++) {
            accO[dt][0] *= sc0; accO[dt][1] *= sc0;
            accO[dt][2] *= sc1; accO[dt][3] *= sc1;
        }

        #pragma unroll
        for (int dt = 0; dt < 16; dt++) {
            #pragma unroll
            for (int s2 = 0; s2 < 2; s2++) {
                int vr = 8 * s2 + l3;
                uint2 y0 = Vs[vr * 132 + dt * 8 + g];
                uint2 y1 = Vs[(vr + 4) * 132 + dt * 8 + g];
                uint32_t bh[2] = {y0.x, y1.x}, bl[2] = {y0.y, y1.y};
                mma_bf16(accO[dt], phi[s2], bh);
                mma_bf16(accO[dt], phi[s2], bl);
                mma_bf16(accO[dt], plo[s2], bh);
            }
        }
    }

    float* AVp = half ? AV1 : AV0;
    float* Mo  = half ? M1 : M0;
    float* Lo  = half ? L1 : L0;
    #pragma unroll
    for (int dt = 0; dt < 16; dt++) {
        int c = dt * 8 + 2 * l3;
        if (r0 < LP_)
            *(float2*)(AVp + ((ll)b * LP_ + r0) * 128 + c) =
                make_float2(accO[dt][0], accO[dt][1]);
        if (r1 < LP_)
            *(float2*)(AVp + ((ll)b * LP_ + r1) * 128 + c) =
                make_float2(accO[dt][2], accO[dt][3]);
    }
    if (l3 == 0) {
        if (r0 < LP_) { Mo[(ll)b * LP_ + r0] = m0_; Lo[(ll)b * LP_ + r0] = l0_; }
        if (r1 < LP_) { Mo[(ll)b * LP_ + r1] = m1_; Lo[(ll)b * LP_ + r1] = l1_; }
    }
}

// ---------------- prep_all: repacks + bq + Wq0 GEMM + Chl GEMM ----------------
__global__ void __launch_bounds__(256)
prep_all(const float* wq_w, const float* wk_w, const float* wv_w,
         const float* wo_w, const float* jp_w, const float* jc_w,
         uint2* wkp, uint2* wvp, uint2* wop, uint2* jpp,
         const float* emb_b, const float* wq_b, float* bq,
         const float* emb_w, float* Wq0,
         const float* cf, const float* jc_b, uint2* Chl)
{
    __shared__ __align__(16) uint2 As[2 * 64 * 12];
    __shared__ __align__(16) uint2 Bs[2 * 8 * 132];
    int y = blockIdx.y;
    if (y == 5) {
        if (blockIdx.x >= 5) return;
        gemm_body<0, 1, 0>(emb_w, nullptr, nullptr, nullptr, nullptr, nullptr,
            nullptr, wq_w, nullptr, Wq0, nullptr,
            E_, D_, D_, D_, D_, 1.f, blockIdx.x * 64, As, Bs);
        return;
    }
    if (y == 6) {
        if (blockIdx.x >= 8) return;
        gemm_body<1, 1, 1>(cf, nullptr, nullptr, nullptr, nullptr, nullptr,
            nullptr, jc_w, jc_b, nullptr, Chl,
            B_*NC_, D_, D_, D_, D_, 1.f, blockIdx.x * 64, As, Bs);
        return;
    }
    if (y == 4) {
        if (blockIdx.x == 0 && threadIdx.x < 128) {
            int n = threadIdx.x;
            float s = wq_b[n];
            for (int k = 0; k < D_; k++) s = fmaf(emb_b[k], wq_w[k * D_ + n], s);
            bq[n] = s;
        }
        return;
    }
    int i = blockIdx.x * 256 + threadIdx.x;
    const float* s; uint2* d;
    switch (y) {
        case 0: s = wk_w; d = wkp; break;
        case 1: s = wv_w; d = wvp; break;
        case 2: s = wo_w; d = wop; break;
        default: s = jp_w; d = jpp; break;
    }
    int kp = i >> 7, n = i & 127;
    d[i] = cvt_pair(s[(2 * kp) * D_ + n], s[(2 * kp + 1) * D_ + n]);
}

__global__ void __launch_bounds__(256, 2)
gemm_qkv(const float* __restrict__ in_pe, const float* __restrict__ Wq0,
         const float* __restrict__ bq, uint2* __restrict__ Qhl,
         const float* __restrict__ in_pfx,
         const uint2* __restrict__ wkp, const float* __restrict__ wk_b,
         uint2* __restrict__ Khl,
         const uint2* __restrict__ wvp, const float* __restrict__ wv_b,
         float* __restrict__ Vf, float inv_sqrt_d)
{
    __shared__ __align__(16) uint2 As[2 * 64 * 12];
    __shared__ __align__(16) uint2 Bs[2 * 8 * 132];
    int m0 = blockIdx.y * 64;
    if (blockIdx.z == 0)
        gemm_body<0, 1, 1>(in_pe, nullptr, nullptr, nullptr, nullptr, nullptr,
            nullptr, Wq0, bq, nullptr, Qhl,
            B_*LP_, D_, E_, E_, D_, inv_sqrt_d, m0, As, Bs);
    else if (blockIdx.z == 1)
        gemm_body<0, 0, 1>(in_pfx, nullptr, nullptr, nullptr, nullptr, nullptr,
            wkp, nullptr, wk_b, nullptr, Khl,
            B_*LP_, D_, D_, D_, D_, 1.f, m0, As, Bs);
    else
        gemm_body<0, 0, 0>(in_pfx, nullptr, nullptr, nullptr, nullptr, nullptr,
            wvp, nullptr, wv_b, Vf, nullptr,
            B_*LP_, D_, D_, D_, D_, 1.f, m0, As, Bs);
}

// ---------------- fused wo+pc: pf = combine(AV)@wo + b ; P = relu(pf)@jp + b --
// GEMM1 writes pf (gmem) + relu'd bf16 pairs into smem (pitch 68), GEMM2
// consumes the smem tile directly. M = 8000 = 125*64 exactly (no tail guards).
__global__ void __launch_bounds__(256, 2)
gemm_wopc(const float* __restrict__ AV0, const float* __restrict__ AV1,
          const float* __restrict__ M0, const float* __restrict__ L0,
          const float* __restrict__ M1, const float* __restrict__ L1,
          const uint2* __restrict__ wop, const float* __restrict__ wo_b,
          const uint2* __restrict__ jpp, const float* __restrict__ jp_b,
          float* __restrict__ pf, float* __restrict__ P)
{
    // union layout: GEMM1 {As[1536], Bs[2112]} ; GEMM2 {pfp[4352], B2[1056]}
    __shared__ __align__(16) uint2 smem_u[5408];   // 43264 B
    int m0 = blockIdx.y * 64;

    gemm_body<4, 0, 2>(AV0, AV1, M0, L0, M1, L1,
        wop, nullptr, wo_b, pf, smem_u /*pfp, pitch 68*/,
        B_*LP_, D_, D_, D_, D_, 1.f, m0, smem_u, smem_u + 1536);

    uint2* pfp = smem_u;
    uint2* B2  = smem_u + 4352;

    int t = threadIdx.x, warp = t >> 5, lane = t & 31;
    int g = lane >> 2, l3 = lane & 3;
    int wm = (warp & 1) * 32, wn = (warp >> 1) * 32;
    int bk = t >> 5, bn = (t & 31) * 4;

    float accP[2][4][4] = {};

    for (int kc = 0; kc < 8; kc++) {
        const uint2* p = jpp + (ll)(kc * 8 + bk) * 128 + bn;
        uint4 u0 = *(const uint4*)p;
        uint4 u1 = *(const uint4*)(p + 2);
        __syncthreads();   // kc==0: pfp writes visible; kc>0: prev MMA reads done
        *(uint4*)&B2[bk * 132 + bn]     = u0;
        *(uint4*)&B2[bk * 132 + bn + 2] = u1;
        __syncthreads();

        uint32_t ahi[2][4], alo[2][4];
        #pragma unroll
        for (int mi = 0; mi < 2; mi++) {
            int rr = wm + mi * 16 + g;
            uint2 x0 = pfp[rr * 68 + kc * 8 + l3];
            uint2 x1 = pfp[(rr + 8) * 68 + kc * 8 + l3];
            uint2 x2 = pfp[rr * 68 + kc * 8 + l3 + 4];
            uint2 x3 = pfp[(rr + 8) * 68 + kc * 8 + l3 + 4];
            ahi[mi][0] = x0.x; alo[mi][0] = x0.y;
            ahi[mi][1] = x1.x; alo[mi][1] = x1.y;
            ahi[mi][2] = x2.x; alo[mi][2] = x2.y;
            ahi[mi][3] = x3.x; alo[mi][3] = x3.y;
        }
        uint32_t bhi[4][2], blo[4][2];
        #pragma unroll
        for (int ni = 0; ni < 4; ni++) {
            int cc = wn + ni * 8 + g;
            uint2 y0 = B2[l3 * 132 + cc];
            uint2 y1 = B2[(l3 + 4) * 132 + cc];
            bhi[ni][0] = y0.x; blo[ni][0] = y0.y;
            bhi[ni][1] = y1.x; blo[ni][1] = y1.y;
        }
        #pragma unroll
        for (int mi = 0; mi < 2; mi++)
            #pragma unroll
            for (int ni = 0; ni < 4; ni++) {
                mma_bf16(accP[mi][ni], ahi[mi], bhi[ni]);
                mma_bf16(accP[mi][ni], ahi[mi], blo[ni]);
                mma_bf16(accP[mi][ni], alo[mi], bhi[ni]);
            }
    }

    #pragma unroll
    for (int mi = 0; mi < 2; mi++)
        #pragma unroll
        for (int ni = 0; ni < 4; ni++) {
            int r0 = m0 + wm + mi * 16 + g;
            int c0 = wn + ni * 8 + 2 * l3;
            float b0 = jp_b[c0], b1 = jp_b[c0 + 1];
            *(float2*)(P + (ll)r0 * 128 + c0) =
                make_float2(accP[mi][ni][0] + b0, accP[mi][ni][1] + b1);
            *(float2*)(P + (ll)(r0 + 8) * 128 + c0) =
                make_float2(accP[mi][ni][2] + b0, accP[mi][ni][3] + b1);
        }
}

// ---------------- A-logits: bf16x3 64x64 GEMM + sigmoid + partial sums -------
__global__ void __launch_bounds__(256, 2)
alogits_kernel(const float* __restrict__ Pm, const uint2* __restrict__ Chl,
               float* __restrict__ Aout, float* __restrict__ Apart)
{
    __shared__ __align__(16) uint2 As[2][768];
    __shared__ __align__(16) uint2 Bs[2][768];
    __shared__ float red[256];

    int b = blockIdx.y, mt = blockIdx.x, m0 = mt * 64;
    const float* A = Pm + (ll)b * LP_ * D_;
    const uint2* Bh = Chl + (ll)b * NC_ * 64;
    float* C = Aout + (ll)b * LP_ * NC_;
    int t = threadIdx.x, warp = t >> 5, lane = t & 31;
    int g = lane >> 2, l3 = lane & 3;
    int wm = (warp & 1) * 32, wn = (warp >> 1) * 16;

    float acc[2][2][4] = {};
    int ar = t >> 2, akf = (t & 3) * 4, akp = (t & 3) * 2;
    uint4 ua, ub;

    auto loadAB = [&](int k0) {
        int gm = m0 + ar;
        float4 rv = make_float4(0.f, 0.f, 0.f, 0.f);
        if (gm < LP_) rv = *(const float4*)(A + (ll)gm * D_ + k0 + akf);
        uint2 p0 = cvt_pair(rv.x, rv.y), p1 = cvt_pair(rv.z, rv.w);
        ua = make_uint4(p0.x, p0.y, p1.x, p1.y);
        ub = *(const uint4*)(Bh + (ll)ar * 64 + (k0 >> 1) + akp);
    };
    auto storeAB = [&](int s) {
        *(uint4*)&As[s][ar * 12 + akp] = ua;
        *(uint4*)&Bs[s][ar * 12 + akp] = ub;
    };
    loadAB(0); storeAB(0);
    __syncthreads();

    for (int it = 0; it < 8; it++) {
        int s = it & 1;
        if (it < 7) loadAB((it + 1) << 4);
        uint32_t ahi[2][4], alo[2][4];
        #pragma unroll
        for (int mi = 0; mi < 2; mi++) {
            int rr = wm + mi * 16 + g;
            uint2 x0 = As[s][rr * 12 + l3];
            uint2 x1 = As[s][(rr + 8) * 12 + l3];
            uint2 x2 = As[s][rr * 12 + l3 + 4];
            uint2 x3 = As[s][(rr + 8) * 12 + l3 + 4];
            ahi[mi][0] = x0.x; alo[mi][0] = x0.y;
            ahi[mi][1] = x1.x; alo[mi][1] = x1.y;
            ahi[mi][2] = x2.x; alo[mi][2] = x2.y;
            ahi[mi][3] = x3.x; alo[mi][3] = x3.y;
        }
        uint32_t bhi[2][2], blo[2][2];
        #pragma unroll
        for (int ni = 0; ni < 2; ni++) {
            int cc = wn + ni * 8 + g;
            uint2 y0 = Bs[s][cc * 12 + l3];
            uint2 y1 = Bs[s][cc * 12 + l3 + 4];
            bhi[ni][0] = y0.x; blo[ni][0] = y0.y;
            bhi[ni][1] = y1.x; blo[ni][1] = y1.y;
        }
        #pragma unroll
        for (int mi = 0; mi < 2; mi++)
            #pragma unroll
            for (int ni = 0; ni < 2; ni++) {
                mma_bf16(acc[mi][ni], ahi[mi], bhi[ni]);
                mma_bf16(acc[mi][ni], ahi[mi], blo[ni]);
                mma_bf16(acc[mi][ni], alo[mi], bhi[ni]);
            }
        if (it < 7) storeAB(s ^ 1);
        __syncthreads();
    }

    float tsum = 0.f;
    #pragma unroll
    for (int mi = 0; mi < 2; mi++)
        #pragma unroll
        for (int ni = 0; ni < 2; ni++) {
            int r0 = m0 + wm + mi * 16 + g;
            int c0 = wn + ni * 8 + 2 * l3;
            if (r0 < LP_) {
                float v0 = 1.f / (1.f + __expf(-acc[mi][ni][0]));
                float v1 = 1.f / (1.f + __expf(-acc[mi][ni][1]));
                *(float2*)(C + (ll)r0 * NC_ + c0) = make_float2(v0, v1);
                tsum += v0 + v1;
            }
            if (r0 + 8 < LP_) {
                float v0 = 1.f / (1.f + __expf(-acc[mi][ni][2]));
                float v1 = 1.f / (1.f + __expf(-acc[mi][ni][3]));
                *(float2*)(C + (ll)(r0 + 8) * NC_ + c0) = make_float2(v0, v1);
                tsum += v0 + v1;
            }
        }
    red[t] = tsum; __syncthreads();
    for (int s2 = 128; s2 > 0; s2 >>= 1) {
        if (t < s2) red[t] += red[t + s2];
        __syncthreads();
    }
    if (t == 0) Apart[b * 16 + mt] = red[0];
}

// ---------------- tanh outer-product weighted reduction ---------------------
__global__ void tanh_outer_kernel(const float* __restrict__ pf,
                                  const float* __restrict__ cf,
                                  const float* __restrict__ A,
                                  float* __restrict__ part)
{
    int b = blockIdx.y, tile = blockIdx.x;
    int d = threadIdx.x;  // 128
    __shared__ float cfs[NC_ * D_];
    for (int i = threadIdx.x; i < NC_ * D_; i += 128)
        cfs[i] = cf[(ll)b * NC_ * D_ + i];
    __syncthreads();
    float acc = 0.f;
    int i0 = tile * ITILE_;
    for (int i = i0; i < i0 + ITILE_; i++) {
        float pv = pf[((ll)b * LP_ + i) * D_ + d];
        const float* Ar = A + ((ll)b * LP_ + i) * NC_;
        #pragma unroll 4
        for (int k = 0; k < NC_; k++) {
            float w = Ar[k];
            float x = pv * cfs[k * D_ + d];
            float th;
            asm("tanh.approx.f32 %0, %1;" : "=f"(th) : "f"(x));
            acc = fmaf(th, w, acc);
        }
    }
    part[((ll)b * NTILE_ + tile) * D_ + d] = acc;
}

__global__ void cp_reduce_kernel(const float* __restrict__ part,
                                 const float* __restrict__ Apart,
                                 float* __restrict__ cp)
{
    int b = blockIdx.x;
    int d = threadIdx.x;  // 128
    float as = 0.f;
    #pragma unroll
    for (int j = 0; j < 16; j++) as += Apart[b * 16 + j];
    float s = 0.f;
    for (int t2 = 0; t2 < NTILE_; t2++)
        s += part[((ll)b * NTILE_ + t2) * D_ + d];
    cp[b * D_ + d] = s / as;
}

// ---------------- skinny GEMM (M = 8 rows) -----------------------------------
template<bool RELU_OUT>
__global__ void __launch_bounds__(256)
skinny_gemm(const float* __restrict__ A, const float* __restrict__ W,
            const float* __restrict__ bias, float* __restrict__ C,
            int N, int K)
{
    __shared__ float As[8 * 1024];
    __shared__ float red[8][8][32];
    int t = threadIdx.x;
    for (int i = t; i < 8 * K; i += 256) As[i] = A[i];
    __syncthreads();
    int n = blockIdx.x * 32 + (t & 31);
    int ks = t >> 5;
    int kseg = K >> 3;
    float acc[8] = {};
    if (n < N) {
        for (int k = ks * kseg; k < (ks + 1) * kseg; k++) {
            float w = W[(ll)k * N + n];
            #pragma unroll
            for (int m = 0; m < 8; m++) acc[m] = fmaf(As[m * K + k], w, acc[m]);
        }
    }
    #pragma unroll
    for (int m = 0; m < 8; m++) red[ks][m][t & 31] = acc[m];
    __syncthreads();
    int m = t >> 5, lnn = t & 31;
    int nn = blockIdx.x * 32 + lnn;
    if (nn < N) {
        float s = 0.f;
        #pragma unroll
        for (int j = 0; j < 8; j++) s += red[j][m][lnn];
        s += bias[nn];
        if (RELU_OUT) s = fmaxf(s, 0.f);
        C[(ll)m * N + nn] = s;
    }
}

// ---------------- launch ------------------------------------------------------
extern "C" void kernel_launch(void* const* d_in, const int* in_sizes, int n_in,
                              void* d_out, int out_size)
{
    const float* in_pe  = (const float*)d_in[0];
    const float* in_pfx = (const float*)d_in[1];
    const float* in_cf  = (const float*)d_in[2];
    const float* emb_w = (const float*)d_in[3];  const float* emb_b = (const float*)d_in[4];
    const float* wq_w  = (const float*)d_in[5];  const float* wq_b  = (const float*)d_in[6];
    const float* wk_w  = (const float*)d_in[7];  const float* wk_b  = (const float*)d_in[8];
    const float* wv_w  = (const float*)d_in[9];  const float* wv_b  = (const float*)d_in[10];
    const float* wo_w  = (const float*)d_in[11]; const float* wo_b  = (const float*)d_in[12];
    const float* jp_w  = (const float*)d_in[13]; const float* jp_b  = (const float*)d_in[14];
    const float* jc_w  = (const float*)d_in[15]; const float* jc_b  = (const float*)d_in[16];
    const float* c1_w  = (const float*)d_in[17]; const float* c1_b  = (const float*)d_in[18];
    const float* c2_w  = (const float*)d_in[19]; const float* c2_b  = (const float*)d_in[20];
    const float* c3_w  = (const float*)d_in[21]; const float* c3_b  = (const float*)d_in[22];
    const float* c4_w  = (const float*)d_in[23]; const float* c4_b  = (const float*)d_in[24];

    uint2 *Qhl, *Khl, *Chl, *wkp, *wvp, *wop, *jpp;
    float *Wq0, *Vf, *AV0, *AV1, *M0, *L0, *M1, *L1, *pf, *P, *A, *bq, *Apart,
          *part, *cp, *h1, *h2, *h3;
    cudaGetSymbolAddress((void**)&Qhl,  g_Qhl);
    cudaGetSymbolAddress((void**)&Khl,  g_Khl);
    cudaGetSymbolAddress((void**)&Chl,  g_Chl);
    cudaGetSymbolAddress((void**)&wkp,  g_wkp);
    cudaGetSymbolAddress((void**)&wvp,  g_wvp);
    cudaGetSymbolAddress((void**)&wop,  g_wop);
    cudaGetSymbolAddress((void**)&jpp,  g_jpp);
    cudaGetSymbolAddress((void**)&Wq0,  g_Wq0);
    cudaGetSymbolAddress((void**)&Vf,   g_Vf);
    cudaGetSymbolAddress((void**)&AV0,  g_AV0);
    cudaGetSymbolAddress((void**)&AV1,  g_AV1);
    cudaGetSymbolAddress((void**)&M0,   g_M0);
    cudaGetSymbolAddress((void**)&L0,   g_L0);
    cudaGetSymbolAddress((void**)&M1,   g_M1);
    cudaGetSymbolAddress((void**)&L1,   g_L1);
    cudaGetSymbolAddress((void**)&pf,   g_pf);
    cudaGetSymbolAddress((void**)&P,    g_P);
    cudaGetSymbolAddress((void**)&A,    g_A);
    cudaGetSymbolAddress((void**)&bq,   g_bq);
    cudaGetSymbolAddress((void**)&Apart,g_Apart);
    cudaGetSymbolAddress((void**)&part, g_part);
    cudaGetSymbolAddress((void**)&cp,   g_cp);
    cudaGetSymbolAddress((void**)&h1,   g_h1);
    cudaGetSymbolAddress((void**)&h2,   g_h2);
    cudaGetSymbolAddress((void**)&h3,   g_h3);

    const float inv_sqrt_d = 0.088388347648318440550f;  // 1/sqrt(128)

    // 0. prep: 4 weight repacks + bq + Wq0 GEMM + Chl GEMM (one launch)
    prep_all<<<dim3(32,7),256>>>(wq_w, wk_w, wv_w, wo_w, jp_w, jc_w,
                                 wkp, wvp, wop, jpp,
                                 emb_b, wq_b, bq, emb_w, Wq0,
                                 in_cf, jc_b, Chl);
    // 1. Q/K/V
    gemm_qkv<<<dim3(1,125,3),256>>>(in_pe, Wq0, bq, Qhl,
                                    in_pfx, wkp, wk_b, Khl,
                                    wvp, wv_b, Vf, inv_sqrt_d);
    // 2. split-KV flash attention -> partial O + (m,l)
    flash_attn<<<dim3(16,2,B_),128>>>(Qhl, Khl, Vf, AV0, AV1, M0, L0, M1, L1);
    // 3. fused: pf = combine(AV)@wo + b ; P = relu(pf)@jp + b (one launch)
    gemm_wopc<<<dim3(1,125),256>>>(AV0, AV1, M0, L0, M1, L1,
                                   wop, wo_b, jpp, jp_b, pf, P);
    // 4. A = sigmoid(P @ C^T) + partial sums
    alogits_kernel<<<dim3(16,B_),256>>>(P, Chl, A, Apart);
    // 5. tanh outer product partials
    tanh_outer_kernel<<<dim3(NTILE_,B_),128>>>(pf, in_cf, A, part);
    // 6. reduce + normalize
    cp_reduce_kernel<<<B_,128>>>(part, Apart, cp);
    // 7-10. classifier MLP
    skinny_gemm<true ><<<32,256>>>(cp, c1_w, c1_b, h1, 1024, D_);
    skinny_gemm<true ><<<32,256>>>(h1, c2_w, c2_b, h2, 1024, 1024);
    skinny_gemm<true ><<<8, 256>>>(h2, c3_w, c3_b, h3, 256, 1024);
    skinny_gemm<false><<<1, 256>>>(h3, c4_w, c4_b, (float*)d_out, 1, 256);
}